// round 13
// baseline (speedup 1.0000x reference)
#include <cuda_runtime.h>
#include <cuda_fp16.h>
#include <cstdint>
#include <math.h>

// ---------------- problem constants ----------------
constexpr int Bsz = 32, T = 1024, D = 256, NH = 2, DK = 128, DH = 1024, L = 4;
constexpr int M_ALL = Bsz * T;          // 32768 rows
constexpr int TPAD  = T + 8;            // conv1 halo (4 each side)
constexpr int BH    = Bsz * NH;         // 64
constexpr float EPS = 1e-5f;

// plane strides (elements)
constexpr long S_HCAT = (long)M_ALL * D;
constexpr long S_QC   = (long)BH * T * DK;
constexpr long S_PC   = (long)BH * T * T;
constexpr long S_AOC  = (long)M_ALL * D;
constexpr long S_HPC  = (long)Bsz * TPAD * D;
constexpr long S_HIDC = (long)M_ALL * DH;
constexpr long S_WQKV = (long)L * 3 * D * D;
constexpr long S_WFC  = (long)L * D * D;
constexpr long S_W1   = (long)L * DH * D * 9;
constexpr long S_W2   = (long)L * D * DH;

// ---------------- device scratch ----------------
// A-role tensors keep hi+lo planes; B-role tensors keep hi only.
__device__ __half g_hcat [2 * S_HCAT];
__device__ float  g_qkvf [(long)M_ALL * 3 * D];
__device__ __half g_qc   [2 * S_QC];
__device__ __half g_kc   [S_QC];          // B only (hi)
__device__ __half g_vc   [S_QC];          // B only (hi), transposed [bh][d][t]
__device__ float  g_scf  [(long)BH * T * T];
__device__ __half g_pc   [2 * S_PC];
__device__ __half g_aoc  [2 * S_AOC];
__device__ __half g_hpc  [2 * S_HPC];
__device__ __half g_hidc [2 * S_HIDC];
__device__ __half g_wqkvc[S_WQKV];        // weights: B only (hi)
__device__ __half g_wfcc [S_WFC];
__device__ __half g_w1c  [S_W1];
__device__ __half g_w2c  [S_W2];
__device__ float  g_nonpad[M_ALL];

// ---------------- mma/ldmatrix/cp.async helpers (portable sm_80+ ISA) -------
__device__ __forceinline__ uint32_t smem_u32(const void* p) {
    uint32_t a;
    asm("{ .reg .u64 t; cvta.to.shared.u64 t, %1; cvt.u32.u64 %0, t; }" : "=r"(a) : "l"(p));
    return a;
}
__device__ __forceinline__ void ldm4(uint32_t* r, uint32_t addr) {
    asm volatile("ldmatrix.sync.aligned.m8n8.x4.shared.b16 {%0,%1,%2,%3},[%4];"
                 : "=r"(r[0]), "=r"(r[1]), "=r"(r[2]), "=r"(r[3]) : "r"(addr));
}
__device__ __forceinline__ void mma16816(float* c, const uint32_t* a, const uint32_t* b) {
    asm volatile("mma.sync.aligned.m16n8k16.row.col.f32.f16.f16.f32 "
                 "{%0,%1,%2,%3},{%4,%5,%6,%7},{%8,%9},{%0,%1,%2,%3};"
                 : "+f"(c[0]), "+f"(c[1]), "+f"(c[2]), "+f"(c[3])
                 : "r"(a[0]), "r"(a[1]), "r"(a[2]), "r"(a[3]), "r"(b[0]), "r"(b[1]));
}
__device__ __forceinline__ void cp_async16(void* sp, const void* gp) {
    uint32_t s = smem_u32(sp);
    asm volatile("cp.async.ca.shared.global [%0], [%1], 16;" :: "r"(s), "l"(gp));
}
__device__ __forceinline__ void cp_commit() {
    asm volatile("cp.async.commit_group;" ::: "memory");
}
template <int N>
__device__ __forceinline__ void cp_wait() {
    asm volatile("cp.async.wait_group %0;" :: "n"(N) : "memory");
}

// ---------------- reductions ----------------
__device__ __forceinline__ float warpSum(float v) {
    #pragma unroll
    for (int o = 16; o; o >>= 1) v += __shfl_xor_sync(0xffffffffu, v, o);
    return v;
}
__device__ __forceinline__ float blockReduceSum(float v) {
    __shared__ float sh[8];
    int lane = threadIdx.x & 31, w = threadIdx.x >> 5;
    v = warpSum(v);
    if (!lane) sh[w] = v;
    __syncthreads();
    if (w == 0) {
        v = (lane < 8) ? sh[lane] : 0.f;
        #pragma unroll
        for (int o = 4; o; o >>= 1) v += __shfl_xor_sync(0xffffffffu, v, o);
        if (!lane) sh[0] = v;
    }
    __syncthreads();
    float r = sh[0];
    __syncthreads();
    return r;
}
__device__ __forceinline__ float blockReduceMax(float v) {
    __shared__ float sh[8];
    int lane = threadIdx.x & 31, w = threadIdx.x >> 5;
    #pragma unroll
    for (int o = 16; o; o >>= 1) v = fmaxf(v, __shfl_xor_sync(0xffffffffu, v, o));
    if (!lane) sh[w] = v;
    __syncthreads();
    if (w == 0) {
        v = (lane < 8) ? sh[lane] : -3.0e38f;
        #pragma unroll
        for (int o = 4; o; o >>= 1) v = fmaxf(v, __shfl_xor_sync(0xffffffffu, v, o));
        if (!lane) sh[0] = v;
    }
    __syncthreads();
    float r = sh[0];
    __syncthreads();
    return r;
}

__device__ __forceinline__ void split_h(float v, __half& h, __half& l) {
    h = __float2half(v);
    l = __float2half(v - __half2float(h));
}
__device__ __forceinline__ uint32_t pack_h2(__half a, __half b) {
    __half2 t; t.x = a; t.y = b;
    return *reinterpret_cast<uint32_t*>(&t);
}

// ---------------- small kernels ----------------
__global__ void embed_k(const int* __restrict__ seq, const int* __restrict__ pos,
                        const float* __restrict__ we, const float* __restrict__ pe,
                        float* __restrict__ x) {
    int r = blockIdx.x, d = threadIdx.x;
    int s = seq[r], p = pos[r];
    x[(long)r * D + d] = we[(long)s * D + d] + pe[(long)p * D + d];
    if (d == 0) g_nonpad[r] = (s != 0) ? 1.f : 0.f;
}

__global__ void ln_cat_k(const float* __restrict__ x, const float* __restrict__ g,
                         const float* __restrict__ bb, __half* __restrict__ out,
                         long S, int padmode) {
    int wid = threadIdx.x >> 5, lane = threadIdx.x & 31;
    long r = (long)blockIdx.x * 8 + wid;
    const float4* px = (const float4*)(x + r * D);
    float4 u = px[lane * 2], w = px[lane * 2 + 1];
    float vals[8] = {u.x, u.y, u.z, u.w, w.x, w.y, w.z, w.w};
    float s = 0.f;
    #pragma unroll
    for (int j = 0; j < 8; j++) s += vals[j];
    s = warpSum(s);
    float mean = s * (1.f / D);
    float q = 0.f;
    #pragma unroll
    for (int j = 0; j < 8; j++) { vals[j] -= mean; q += vals[j] * vals[j]; }
    q = warpSum(q);
    float rstd = rsqrtf(q * (1.f / D) + EPS);
    int col = lane * 8;
    const float4* pg = (const float4*)(g + col);
    const float4* pb = (const float4*)(bb + col);
    float4 g0 = pg[0], g1 = pg[1], b0 = pb[0], b1 = pb[1];
    float gg[8] = {g0.x, g0.y, g0.z, g0.w, g1.x, g1.y, g1.z, g1.w};
    float bbv[8] = {b0.x, b0.y, b0.z, b0.w, b1.x, b1.y, b1.z, b1.w};
    uint32_t hi[4], lo[4];
    #pragma unroll
    for (int j = 0; j < 4; j++) {
        float y0 = vals[2 * j] * rstd * gg[2 * j] + bbv[2 * j];
        float y1 = vals[2 * j + 1] * rstd * gg[2 * j + 1] + bbv[2 * j + 1];
        __half h0, l0, h1, l1;
        split_h(y0, h0, l0); split_h(y1, h1, l1);
        hi[j] = pack_h2(h0, h1); lo[j] = pack_h2(l0, l1);
    }
    long orow;
    if (padmode) { long b = r / T, t = r % T; orow = b * TPAD + t + 4; }
    else orow = r;
    long ob = orow * D + col;
    *(uint4*)(out + ob)      = *(uint4*)hi;
    *(uint4*)(out + S + ob)  = *(uint4*)lo;
}

__global__ void zero_halo_k(__half* __restrict__ hp, long S) {
    int idx = blockIdx.x * blockDim.x + threadIdx.x;
    int b = idx / (8 * D);
    int rr = (idx / D) % 8;
    int d = idx % D;
    int t = (rr < 4) ? rr : (T + 4 + rr - 4);
    long o = ((long)b * TPAD + t) * D + d;
    hp[o] = __float2half(0.f);
    hp[S + o] = __float2half(0.f);
}

// single-plane (hi) weight convert
__global__ void cvt_w_k(const float* __restrict__ w, __half* __restrict__ out, long n) {
    long i = (long)blockIdx.x * blockDim.x + threadIdx.x;
    if (i >= n) return;
    out[i] = __float2half(w[i]);
}

__global__ void cvt_w1_k(const float* __restrict__ w, __half* __restrict__ out) {
    long i = (long)blockIdx.x * blockDim.x + threadIdx.x;
    const long total = S_W1;
    if (i >= total) return;
    long base = i / (D * 9);
    int p = (int)(i % (D * 9));
    int kk = p / D, ii = p % D;
    out[i] = __float2half(w[base * (D * 9) + (long)ii * 9 + kk]);
}

// split qkv fp32 -> q (hi+lo), k (hi), v (hi, transposed [bh][d][t])
__global__ void cvt_qkv_k(const float* __restrict__ qkv,
                          __half* __restrict__ qc, __half* __restrict__ kc,
                          __half* __restrict__ vc, long S) {
    long idx = (long)blockIdx.x * blockDim.x + threadIdx.x;   // M_ALL*64
    long r = idx >> 6; int c4 = (int)(idx & 63);
    int b = (int)(r / T), t = (int)(r % T);
    int c = c4 * 4; int h = c >> 7; int d = c & 127;
    long src = r * (3 * D);
    float4 q = *(const float4*)(qkv + src + c);
    float4 k = *(const float4*)(qkv + src + D + c);
    float4 v = *(const float4*)(qkv + src + 2 * D + c);
    long bh = (long)b * NH + h;
    long qdst = (bh * T + t) * DK + d;
    {
        float a[4] = {q.x, q.y, q.z, q.w};
        __half hh[4], ll[4];
        #pragma unroll
        for (int j = 0; j < 4; j++) split_h(a[j], hh[j], ll[j]);
        uint32_t hu[2] = {pack_h2(hh[0], hh[1]), pack_h2(hh[2], hh[3])};
        uint32_t lu[2] = {pack_h2(ll[0], ll[1]), pack_h2(ll[2], ll[3])};
        *(uint2*)(qc + qdst) = *(uint2*)hu;
        *(uint2*)(qc + S + qdst) = *(uint2*)lu;
    }
    {
        uint32_t hu[2] = {pack_h2(__float2half(k.x), __float2half(k.y)),
                          pack_h2(__float2half(k.z), __float2half(k.w))};
        *(uint2*)(kc + qdst) = *(uint2*)hu;
    }
    {
        float a[4] = {v.x, v.y, v.z, v.w};
        #pragma unroll
        for (int j = 0; j < 4; j++) {
            long vdst = (bh * DK + d + j) * T + t;
            vc[vdst] = __float2half(a[j]);
        }
    }
}

// softmax: fp32 scores -> hi/lo fp16 P
__global__ void softmax_cat_k(const float* __restrict__ sc, const int* __restrict__ seq,
                              __half* __restrict__ out, long S) {
    long row = blockIdx.x;
    int b = (int)(row / ((long)NH * T));
    const float* p = sc + row * T;
    const int* sq = seq + (long)b * T;
    const float scale = 0.08838834764831845f;
    int t = threadIdx.x;
    float4 v4 = *(const float4*)(p + t * 4);
    int4 s4 = *(const int4*)(sq + t * 4);
    float vals[4] = {v4.x, v4.y, v4.z, v4.w};
    int ss[4] = {s4.x, s4.y, s4.z, s4.w};
    float mx = -3.0e38f;
    #pragma unroll
    for (int j = 0; j < 4; j++) {
        vals[j] = (ss[j] == 0) ? -3.0e38f : vals[j] * scale;
        mx = fmaxf(mx, vals[j]);
    }
    float M = blockReduceMax(mx);
    float s = 0.f;
    #pragma unroll
    for (int j = 0; j < 4; j++) { vals[j] = __expf(vals[j] - M); s += vals[j]; }
    float Ssum = blockReduceSum(s);
    float inv = 1.f / Ssum;
    __half hh[4], ll[4];
    #pragma unroll
    for (int j = 0; j < 4; j++) split_h(vals[j] * inv, hh[j], ll[j]);
    uint32_t hu[2] = {pack_h2(hh[0], hh[1]), pack_h2(hh[2], hh[3])};
    uint32_t lu[2] = {pack_h2(ll[0], ll[1]), pack_h2(ll[2], ll[3])};
    long ob = row * T + t * 4;
    *(uint2*)(out + ob) = *(uint2*)hu;
    *(uint2*)(out + S + ob) = *(uint2*)lu;
}

__global__ void copy_np_k(float* __restrict__ out) {
    int i = blockIdx.x * blockDim.x + threadIdx.x;
    if (i < M_ALL) out[i] = g_nonpad[i];
}

// ---------------- HMMA split-fp16 GEMM (2-pass), cp.async.ca 3-stage --------
// C[m,n] = sum_k A[m,k]*B[n,k]; A has hi+lo planes (stride Sa), B hi only.
// Tile 128x128, 8 warps (4x2 grid, warp tile 32x64), K-chunk 32.
// __launch_bounds__(256, 2): cap regs at 128 so TWO CTAs co-reside per SM.
// MMA emission: full hi-sweep then full lo-sweep per ks so the two writes to
// each accumulator are 16 MMAs apart (no back-to-back RAW on accumulators).
constexpr int TG_STRIDE = 40;                       // fp16 elems per smem row (pad)
constexpr int TG_PLANE  = 128 * TG_STRIDE;          // elems per plane
constexpr int TG_STAGE  = 3 * TG_PLANE;             // Ahi, Alo, Bhi per stage
constexpr int TG_STAGES = 3;
constexpr int TG_SMEM   = (int)(TG_STAGES * TG_STAGE * sizeof(__half)); // 92160B

__global__ void __launch_bounds__(256, 2)
tgemm(const __half* __restrict__ A, int lda, long Sa, long aSb, long aSh,
      const __half* __restrict__ B, int ldb, long bSb, long bSh,
      float* __restrict__ Cf, __half* __restrict__ Chi, long Sc,
      int ldc, long cSb, long cSh,
      int K, int H,
      const float* __restrict__ bias, const float* __restrict__ resid,
      const float* __restrict__ mask, int relu) {
    extern __shared__ __half smem[];

    int tid = threadIdx.x, wid = tid >> 5, lane = tid & 31;
    int warp_m = wid & 3, warp_n = wid >> 2;

    int z = blockIdx.z, zb = z / H, zh = z - zb * H;
    A += (long)zb * aSb + (long)zh * aSh;
    B += (long)zb * bSb + (long)zh * bSh;
    long cOff = (long)zb * cSb + (long)zh * cSh;
    if (Cf)    Cf += cOff;
    if (Chi)   Chi += cOff;
    if (resid) resid += cOff;
    int m0 = blockIdx.x * 128, n0 = blockIdx.y * 128;

    int lr = tid >> 2;            // 0..63 (+64 second row)
    int lc = (tid & 3) * 8;       // col (fp16 elems), 16B granules

    auto load_chunk = [&](int ci, int stg) {
        __half* S = smem + stg * TG_STAGE;
        int k0 = ci << 5;
        #pragma unroll
        for (int j = 0; j < 2; j++) {
            int r = lr + j * 64;
            long ak = (long)(m0 + r) * lda + k0 + lc;
            long bk = (long)(n0 + r) * ldb + k0 + lc;
            cp_async16(&S[r * TG_STRIDE + lc],                A + ak);
            cp_async16(&S[TG_PLANE + r * TG_STRIDE + lc],     A + Sa + ak);
            cp_async16(&S[2 * TG_PLANE + r * TG_STRIDE + lc], B + bk);
        }
        cp_commit();
    };

    float acc[2][8][4];
    #pragma unroll
    for (int a = 0; a < 2; a++)
        #pragma unroll
        for (int b = 0; b < 8; b++)
            #pragma unroll
            for (int c = 0; c < 4; c++) acc[a][b][c] = 0.f;

    int nc = K >> 5;
    load_chunk(0, 0);
    if (nc > 1) load_chunk(1, 1);

    int stg = 0;
    for (int i = 0; i < nc; i++) {
        if (i + 1 < nc) cp_wait<1>(); else cp_wait<0>();
        __syncthreads();
        if (i + 2 < nc) load_chunk(i + 2, (stg + 2) % TG_STAGES);

        const __half* Ss = smem + stg * TG_STAGE;
        #pragma unroll
        for (int ks = 0; ks < 2; ks++) {
            uint32_t ah[2][4], al[2][4], bh[4][4];
            #pragma unroll
            for (int mt = 0; mt < 2; mt++) {
                int row = warp_m * 32 + mt * 16 + (lane & 15);
                int col = ks * 16 + ((lane >> 4) << 3);
                uint32_t ad = smem_u32(Ss + row * TG_STRIDE + col);
                ldm4(ah[mt], ad);
                ldm4(al[mt], ad + TG_PLANE * 2);
            }
            #pragma unroll
            for (int tp = 0; tp < 4; tp++) {
                int row = warp_n * 64 + tp * 16 + ((lane >> 4) << 3) + (lane & 7);
                int col = ks * 16 + (((lane >> 3) & 1) << 3);
                uint32_t bd = smem_u32(Ss + 2 * TG_PLANE + row * TG_STRIDE + col);
                ldm4(bh[tp], bd);
            }
            // hi sweep: 16 independent MMAs
            #pragma unroll
            for (int tp = 0; tp < 4; tp++)
                #pragma unroll
                for (int mt = 0; mt < 2; mt++)
                    #pragma unroll
                    for (int nt = 0; nt < 2; nt++)
                        mma16816(acc[mt][tp * 2 + nt], ah[mt], bh[tp] + nt * 2);
            // lo sweep: second touch of each accumulator, 16 MMAs later
            #pragma unroll
            for (int tp = 0; tp < 4; tp++)
                #pragma unroll
                for (int mt = 0; mt < 2; mt++)
                    #pragma unroll
                    for (int nt = 0; nt < 2; nt++)
                        mma16816(acc[mt][tp * 2 + nt], al[mt], bh[tp] + nt * 2);
        }
        stg = (stg + 1) % TG_STAGES;
    }

    // epilogue: direct stores
    #pragma unroll
    for (int mt = 0; mt < 2; mt++) {
        #pragma unroll
        for (int nt8 = 0; nt8 < 8; nt8++) {
            float* c = acc[mt][nt8];
            int row0 = m0 + warp_m * 32 + mt * 16 + (lane >> 2);
            int col  = n0 + warp_n * 64 + nt8 * 8 + (lane & 3) * 2;
            #pragma unroll
            for (int half = 0; half < 2; half++) {
                int m = row0 + half * 8;
                float v0 = c[half * 2], v1 = c[half * 2 + 1];
                if (bias) { v0 += bias[col]; v1 += bias[col + 1]; }
                if (relu) { v0 = fmaxf(v0, 0.f); v1 = fmaxf(v1, 0.f); }
                long co = (long)m * ldc + col;
                if (resid) { v0 += resid[co]; v1 += resid[co + 1]; }
                if (mask) { float mk = mask[m]; v0 *= mk; v1 *= mk; }
                if (Cf) { float2 o; o.x = v0; o.y = v1; *(float2*)(Cf + co) = o; }
                if (Chi) {
                    __half h0, l0, h1, l1;
                    split_h(v0, h0, l0); split_h(v1, h1, l1);
                    *(uint32_t*)(Chi + co)      = pack_h2(h0, h1);
                    *(uint32_t*)(Chi + Sc + co) = pack_h2(l0, l1);
                }
            }
        }
    }
}

// ---------------- host orchestration ----------------
extern "C" void kernel_launch(void* const* d_in, const int* in_sizes, int n_in,
                              void* d_out, int out_size) {
    const int*   src_seq  = (const int*)  d_in[0];
    const int*   src_pos  = (const int*)  d_in[1];
    const float* word_emb = (const float*)d_in[2];
    const float* pos_emb  = (const float*)d_in[3];
    const float* qkv_w    = (const float*)d_in[4];
    const float* qkv_b    = (const float*)d_in[5];
    const float* fc_w     = (const float*)d_in[6];
    const float* fc_b     = (const float*)d_in[7];
    const float* ln1_g    = (const float*)d_in[8];
    const float* ln1_b    = (const float*)d_in[9];
    const float* conv1_w  = (const float*)d_in[10];
    const float* conv1_b  = (const float*)d_in[11];
    const float* conv2_w  = (const float*)d_in[12];
    const float* conv2_b  = (const float*)d_in[13];
    const float* ln2_g    = (const float*)d_in[14];
    const float* ln2_b    = (const float*)d_in[15];

    float* x = (float*)d_out;

    cudaFuncSetAttribute(tgemm, cudaFuncAttributeMaxDynamicSharedMemorySize, TG_SMEM);

    __half *p_hcat, *p_qc, *p_kc, *p_vc, *p_pc, *p_aoc, *p_hpc, *p_hidc;
    __half *p_wqkv, *p_wfc, *p_w1, *p_w2;
    float *p_qkvf, *p_scf, *p_np;
    cudaGetSymbolAddress((void**)&p_hcat, g_hcat);
    cudaGetSymbolAddress((void**)&p_qkvf, g_qkvf);
    cudaGetSymbolAddress((void**)&p_qc,   g_qc);
    cudaGetSymbolAddress((void**)&p_kc,   g_kc);
    cudaGetSymbolAddress((void**)&p_vc,   g_vc);
    cudaGetSymbolAddress((void**)&p_scf,  g_scf);
    cudaGetSymbolAddress((void**)&p_pc,   g_pc);
    cudaGetSymbolAddress((void**)&p_aoc,  g_aoc);
    cudaGetSymbolAddress((void**)&p_hpc,  g_hpc);
    cudaGetSymbolAddress((void**)&p_hidc, g_hidc);
    cudaGetSymbolAddress((void**)&p_wqkv, g_wqkvc);
    cudaGetSymbolAddress((void**)&p_wfc,  g_wfcc);
    cudaGetSymbolAddress((void**)&p_w1,   g_w1c);
    cudaGetSymbolAddress((void**)&p_w2,   g_w2c);
    cudaGetSymbolAddress((void**)&p_np,   g_nonpad);

    // minimal prep before first GEMM (so ncu capture slot #4 = tgemm qkv)
    cvt_w_k<<<(int)((S_WQKV + 255) / 256), 256>>>(qkv_w, p_wqkv, S_WQKV);
    embed_k<<<M_ALL, D>>>(src_seq, src_pos, word_emb, pos_emb, x);

    for (int l = 0; l < L; l++) {
        // ---- attention ----
        ln_cat_k<<<M_ALL / 8, 256>>>(x, ln1_g + l * D, ln1_b + l * D, p_hcat, S_HCAT, 0);

        tgemm<<<dim3(M_ALL / 128, 6, 1), 256, TG_SMEM>>>(
            p_hcat, D, S_HCAT, 0, 0,
            p_wqkv + (long)l * 3 * D * D, D, 0, 0,
            p_qkvf, nullptr, 0, 3 * D, 0, 0,
            D, 1, qkv_b + (long)l * 3 * D, nullptr, nullptr, 0);

        if (l == 0) {
            // rest of one-time prep (before first use below)
            zero_halo_k<<<(Bsz * 8 * D) / 256, 256>>>(p_hpc, S_HPC);
            cvt_w_k<<<(int)((S_WFC + 255) / 256), 256>>>(fc_w, p_wfc, S_WFC);
            cvt_w1_k<<<(int)((S_W1 + 255) / 256), 256>>>(conv1_w, p_w1);
            cvt_w_k<<<(int)((S_W2 + 255) / 256), 256>>>(conv2_w, p_w2, S_W2);
        }

        cvt_qkv_k<<<(int)(((long)M_ALL * 64 + 255) / 256), 256>>>(p_qkvf, p_qc, p_kc, p_vc, S_QC);

        tgemm<<<dim3(8, 8, BH), 256, TG_SMEM>>>(
            p_qc, DK, S_QC, (long)NH * T * DK, (long)T * DK,
            p_kc, DK, (long)NH * T * DK, (long)T * DK,
            p_scf, nullptr, 0, T, (long)NH * T * T, (long)T * T,
            DK, NH, nullptr, nullptr, nullptr, 0);

        softmax_cat_k<<<BH * T, 256>>>(p_scf, src_seq, p_pc, S_PC);

        tgemm<<<dim3(8, 1, BH), 256, TG_SMEM>>>(
            p_pc, T, S_PC, (long)NH * T * T, (long)T * T,
            p_vc, T, (long)NH * DK * T, (long)DK * T,
            nullptr, p_aoc, S_AOC, D, (long)T * D, DK,
            T, NH, nullptr, nullptr, nullptr, 0);

        tgemm<<<dim3(M_ALL / 128, 2, 1), 256, TG_SMEM>>>(
            p_aoc, D, S_AOC, 0, 0,
            p_wfc + (long)l * D * D, D, 0, 0,
            x, nullptr, 0, D, 0, 0,
            D, 1, fc_b + (long)l * D, x, p_np, 0);

        // ---- conv FFN ----
        ln_cat_k<<<M_ALL / 8, 256>>>(x, ln2_g + l * D, ln2_b + l * D, p_hpc, S_HPC, 1);

        tgemm<<<dim3(8, 8, Bsz), 256, TG_SMEM>>>(
            p_hpc, D, S_HPC, (long)TPAD * D, 0,
            p_w1 + (long)l * DH * D * 9, D * 9, 0, 0,
            nullptr, p_hidc, S_HIDC, DH, (long)T * DH, 0,
            D * 9, 1, conv1_b + (long)l * DH, nullptr, nullptr, 1);

        tgemm<<<dim3(M_ALL / 128, 2, 1), 256, TG_SMEM>>>(
            p_hidc, DH, S_HIDC, 0, 0,
            p_w2 + (long)l * D * DH, DH, 0, 0,
            x, nullptr, 0, D, 0, 0,
            DH, 1, conv2_b + (long)l * D, x, p_np, 0);
    }

    if (out_size >= M_ALL * D + M_ALL) {
        copy_np_k<<<M_ALL / 256, 256>>>((float*)d_out + (long)M_ALL * D);
    }
}

// round 14
// speedup vs baseline: 1.1060x; 1.1060x over previous
#include <cuda_runtime.h>
#include <cuda_fp16.h>
#include <cstdint>
#include <math.h>

// ---------------- problem constants ----------------
constexpr int Bsz = 32, T = 1024, D = 256, NH = 2, DK = 128, DH = 1024, L = 4;
constexpr int M_ALL = Bsz * T;          // 32768 rows
constexpr int TPAD  = T + 8;            // conv1 halo (4 each side)
constexpr int BH    = Bsz * NH;         // 64
constexpr float EPS = 1e-5f;

// plane strides (elements)
constexpr long S_HCAT = (long)M_ALL * D;
constexpr long S_QC   = (long)BH * T * DK;
constexpr long S_PC   = (long)BH * T * T;
constexpr long S_AOC  = (long)M_ALL * D;
constexpr long S_HPC  = (long)Bsz * TPAD * D;
constexpr long S_HIDC = (long)M_ALL * DH;
constexpr long S_WQKV = (long)L * 3 * D * D;
constexpr long S_WFC  = (long)L * D * D;
constexpr long S_W1   = (long)L * DH * D * 9;
constexpr long S_W2   = (long)L * D * DH;

// ---------------- device scratch ----------------
// A-role tensors keep hi+lo planes; B-role tensors keep hi only.
__device__ __half g_hcat [2 * S_HCAT];
__device__ float  g_qkvf [(long)M_ALL * 3 * D];
__device__ __half g_qc   [2 * S_QC];
__device__ __half g_kc   [S_QC];          // B only (hi)
__device__ __half g_vc   [S_QC];          // B only (hi), transposed [bh][d][t]
__device__ float  g_scf  [(long)BH * T * T];
__device__ __half g_pc   [2 * S_PC];
__device__ __half g_aoc  [2 * S_AOC];
__device__ __half g_hpc  [2 * S_HPC];
__device__ __half g_hidc [2 * S_HIDC];
__device__ __half g_wqkvc[S_WQKV];        // weights: B only (hi)
__device__ __half g_wfcc [S_WFC];
__device__ __half g_w1c  [S_W1];
__device__ __half g_w2c  [S_W2];
__device__ float  g_nonpad[M_ALL];

// ---------------- mma/ldmatrix/cp.async helpers (portable sm_80+ ISA) -------
__device__ __forceinline__ uint32_t smem_u32(const void* p) {
    uint32_t a;
    asm("{ .reg .u64 t; cvta.to.shared.u64 t, %1; cvt.u32.u64 %0, t; }" : "=r"(a) : "l"(p));
    return a;
}
__device__ __forceinline__ void ldm4(uint32_t* r, uint32_t addr) {
    asm volatile("ldmatrix.sync.aligned.m8n8.x4.shared.b16 {%0,%1,%2,%3},[%4];"
                 : "=r"(r[0]), "=r"(r[1]), "=r"(r[2]), "=r"(r[3]) : "r"(addr));
}
__device__ __forceinline__ void mma16816(float* c, const uint32_t* a, const uint32_t* b) {
    asm volatile("mma.sync.aligned.m16n8k16.row.col.f32.f16.f16.f32 "
                 "{%0,%1,%2,%3},{%4,%5,%6,%7},{%8,%9},{%0,%1,%2,%3};"
                 : "+f"(c[0]), "+f"(c[1]), "+f"(c[2]), "+f"(c[3])
                 : "r"(a[0]), "r"(a[1]), "r"(a[2]), "r"(a[3]), "r"(b[0]), "r"(b[1]));
}
__device__ __forceinline__ void cp_async16(void* sp, const void* gp) {
    uint32_t s = smem_u32(sp);
    asm volatile("cp.async.ca.shared.global [%0], [%1], 16;" :: "r"(s), "l"(gp));
}
__device__ __forceinline__ void cp_commit() {
    asm volatile("cp.async.commit_group;" ::: "memory");
}
template <int N>
__device__ __forceinline__ void cp_wait() {
    asm volatile("cp.async.wait_group %0;" :: "n"(N) : "memory");
}

// ---------------- reductions ----------------
__device__ __forceinline__ float warpSum(float v) {
    #pragma unroll
    for (int o = 16; o; o >>= 1) v += __shfl_xor_sync(0xffffffffu, v, o);
    return v;
}
__device__ __forceinline__ float blockReduceSum(float v) {
    __shared__ float sh[8];
    int lane = threadIdx.x & 31, w = threadIdx.x >> 5;
    v = warpSum(v);
    if (!lane) sh[w] = v;
    __syncthreads();
    if (w == 0) {
        v = (lane < 8) ? sh[lane] : 0.f;
        #pragma unroll
        for (int o = 4; o; o >>= 1) v += __shfl_xor_sync(0xffffffffu, v, o);
        if (!lane) sh[0] = v;
    }
    __syncthreads();
    float r = sh[0];
    __syncthreads();
    return r;
}
__device__ __forceinline__ float blockReduceMax(float v) {
    __shared__ float sh[8];
    int lane = threadIdx.x & 31, w = threadIdx.x >> 5;
    #pragma unroll
    for (int o = 16; o; o >>= 1) v = fmaxf(v, __shfl_xor_sync(0xffffffffu, v, o));
    if (!lane) sh[w] = v;
    __syncthreads();
    if (w == 0) {
        v = (lane < 8) ? sh[lane] : -3.0e38f;
        #pragma unroll
        for (int o = 4; o; o >>= 1) v = fmaxf(v, __shfl_xor_sync(0xffffffffu, v, o));
        if (!lane) sh[0] = v;
    }
    __syncthreads();
    float r = sh[0];
    __syncthreads();
    return r;
}

__device__ __forceinline__ void split_h(float v, __half& h, __half& l) {
    h = __float2half(v);
    l = __float2half(v - __half2float(h));
}
__device__ __forceinline__ uint32_t pack_h2(__half a, __half b) {
    __half2 t; t.x = a; t.y = b;
    return *reinterpret_cast<uint32_t*>(&t);
}

// ---------------- small kernels ----------------
__global__ void embed_k(const int* __restrict__ seq, const int* __restrict__ pos,
                        const float* __restrict__ we, const float* __restrict__ pe,
                        float* __restrict__ x) {
    int r = blockIdx.x, d = threadIdx.x;
    int s = seq[r], p = pos[r];
    x[(long)r * D + d] = we[(long)s * D + d] + pe[(long)p * D + d];
    if (d == 0) g_nonpad[r] = (s != 0) ? 1.f : 0.f;
}

__global__ void ln_cat_k(const float* __restrict__ x, const float* __restrict__ g,
                         const float* __restrict__ bb, __half* __restrict__ out,
                         long S, int padmode) {
    int wid = threadIdx.x >> 5, lane = threadIdx.x & 31;
    long r = (long)blockIdx.x * 8 + wid;
    const float4* px = (const float4*)(x + r * D);
    float4 u = px[lane * 2], w = px[lane * 2 + 1];
    float vals[8] = {u.x, u.y, u.z, u.w, w.x, w.y, w.z, w.w};
    float s = 0.f;
    #pragma unroll
    for (int j = 0; j < 8; j++) s += vals[j];
    s = warpSum(s);
    float mean = s * (1.f / D);
    float q = 0.f;
    #pragma unroll
    for (int j = 0; j < 8; j++) { vals[j] -= mean; q += vals[j] * vals[j]; }
    q = warpSum(q);
    float rstd = rsqrtf(q * (1.f / D) + EPS);
    int col = lane * 8;
    const float4* pg = (const float4*)(g + col);
    const float4* pb = (const float4*)(bb + col);
    float4 g0 = pg[0], g1 = pg[1], b0 = pb[0], b1 = pb[1];
    float gg[8] = {g0.x, g0.y, g0.z, g0.w, g1.x, g1.y, g1.z, g1.w};
    float bbv[8] = {b0.x, b0.y, b0.z, b0.w, b1.x, b1.y, b1.z, b1.w};
    uint32_t hi[4], lo[4];
    #pragma unroll
    for (int j = 0; j < 4; j++) {
        float y0 = vals[2 * j] * rstd * gg[2 * j] + bbv[2 * j];
        float y1 = vals[2 * j + 1] * rstd * gg[2 * j + 1] + bbv[2 * j + 1];
        __half h0, l0, h1, l1;
        split_h(y0, h0, l0); split_h(y1, h1, l1);
        hi[j] = pack_h2(h0, h1); lo[j] = pack_h2(l0, l1);
    }
    long orow;
    if (padmode) { long b = r / T, t = r % T; orow = b * TPAD + t + 4; }
    else orow = r;
    long ob = orow * D + col;
    *(uint4*)(out + ob)      = *(uint4*)hi;
    *(uint4*)(out + S + ob)  = *(uint4*)lo;
}

__global__ void zero_halo_k(__half* __restrict__ hp, long S) {
    int idx = blockIdx.x * blockDim.x + threadIdx.x;
    int b = idx / (8 * D);
    int rr = (idx / D) % 8;
    int d = idx % D;
    int t = (rr < 4) ? rr : (T + 4 + rr - 4);
    long o = ((long)b * TPAD + t) * D + d;
    hp[o] = __float2half(0.f);
    hp[S + o] = __float2half(0.f);
}

// single-plane (hi) weight convert
__global__ void cvt_w_k(const float* __restrict__ w, __half* __restrict__ out, long n) {
    long i = (long)blockIdx.x * blockDim.x + threadIdx.x;
    if (i >= n) return;
    out[i] = __float2half(w[i]);
}

__global__ void cvt_w1_k(const float* __restrict__ w, __half* __restrict__ out) {
    long i = (long)blockIdx.x * blockDim.x + threadIdx.x;
    const long total = S_W1;
    if (i >= total) return;
    long base = i / (D * 9);
    int p = (int)(i % (D * 9));
    int kk = p / D, ii = p % D;
    out[i] = __float2half(w[base * (D * 9) + (long)ii * 9 + kk]);
}

// split qkv fp32 -> q (hi+lo), k (hi), v (hi, transposed [bh][d][t])
__global__ void cvt_qkv_k(const float* __restrict__ qkv,
                          __half* __restrict__ qc, __half* __restrict__ kc,
                          __half* __restrict__ vc, long S) {
    long idx = (long)blockIdx.x * blockDim.x + threadIdx.x;   // M_ALL*64
    long r = idx >> 6; int c4 = (int)(idx & 63);
    int b = (int)(r / T), t = (int)(r % T);
    int c = c4 * 4; int h = c >> 7; int d = c & 127;
    long src = r * (3 * D);
    float4 q = *(const float4*)(qkv + src + c);
    float4 k = *(const float4*)(qkv + src + D + c);
    float4 v = *(const float4*)(qkv + src + 2 * D + c);
    long bh = (long)b * NH + h;
    long qdst = (bh * T + t) * DK + d;
    {
        float a[4] = {q.x, q.y, q.z, q.w};
        __half hh[4], ll[4];
        #pragma unroll
        for (int j = 0; j < 4; j++) split_h(a[j], hh[j], ll[j]);
        uint32_t hu[2] = {pack_h2(hh[0], hh[1]), pack_h2(hh[2], hh[3])};
        uint32_t lu[2] = {pack_h2(ll[0], ll[1]), pack_h2(ll[2], ll[3])};
        *(uint2*)(qc + qdst) = *(uint2*)hu;
        *(uint2*)(qc + S + qdst) = *(uint2*)lu;
    }
    {
        uint32_t hu[2] = {pack_h2(__float2half(k.x), __float2half(k.y)),
                          pack_h2(__float2half(k.z), __float2half(k.w))};
        *(uint2*)(kc + qdst) = *(uint2*)hu;
    }
    {
        float a[4] = {v.x, v.y, v.z, v.w};
        #pragma unroll
        for (int j = 0; j < 4; j++) {
            long vdst = (bh * DK + d + j) * T + t;
            vc[vdst] = __float2half(a[j]);
        }
    }
}

// softmax: fp32 scores -> hi/lo fp16 P
__global__ void softmax_cat_k(const float* __restrict__ sc, const int* __restrict__ seq,
                              __half* __restrict__ out, long S) {
    long row = blockIdx.x;
    int b = (int)(row / ((long)NH * T));
    const float* p = sc + row * T;
    const int* sq = seq + (long)b * T;
    const float scale = 0.08838834764831845f;
    int t = threadIdx.x;
    float4 v4 = *(const float4*)(p + t * 4);
    int4 s4 = *(const int4*)(sq + t * 4);
    float vals[4] = {v4.x, v4.y, v4.z, v4.w};
    int ss[4] = {s4.x, s4.y, s4.z, s4.w};
    float mx = -3.0e38f;
    #pragma unroll
    for (int j = 0; j < 4; j++) {
        vals[j] = (ss[j] == 0) ? -3.0e38f : vals[j] * scale;
        mx = fmaxf(mx, vals[j]);
    }
    float M = blockReduceMax(mx);
    float s = 0.f;
    #pragma unroll
    for (int j = 0; j < 4; j++) { vals[j] = __expf(vals[j] - M); s += vals[j]; }
    float Ssum = blockReduceSum(s);
    float inv = 1.f / Ssum;
    __half hh[4], ll[4];
    #pragma unroll
    for (int j = 0; j < 4; j++) split_h(vals[j] * inv, hh[j], ll[j]);
    uint32_t hu[2] = {pack_h2(hh[0], hh[1]), pack_h2(hh[2], hh[3])};
    uint32_t lu[2] = {pack_h2(ll[0], ll[1]), pack_h2(ll[2], ll[3])};
    long ob = row * T + t * 4;
    *(uint2*)(out + ob) = *(uint2*)hu;
    *(uint2*)(out + S + ob) = *(uint2*)lu;
}

__global__ void copy_np_k(float* __restrict__ out) {
    int i = blockIdx.x * blockDim.x + threadIdx.x;
    if (i < M_ALL) out[i] = g_nonpad[i];
}

// ---------------- HMMA split-fp16 GEMM, cp.async.ca 3-stage -----------------
// C[m,n] = sum_k A[m,k]*B[n,k]; A has hi(+lo) planes (stride Sa), B hi only.
// use_lo: 1 = two passes (hi*hi + lo_a*hi_b); 0 = hi*hi only (half the MMAs).
// Tile 128x128, 8 warps (4x2 grid, warp tile 32x64), K-chunk 32.
// __launch_bounds__(256, 2): cap regs at 128 so TWO CTAs co-reside per SM.
constexpr int TG_STRIDE = 40;                       // fp16 elems per smem row (pad)
constexpr int TG_PLANE  = 128 * TG_STRIDE;          // elems per plane
constexpr int TG_STAGE  = 3 * TG_PLANE;             // Ahi, Alo, Bhi per stage
constexpr int TG_STAGES = 3;
constexpr int TG_SMEM   = (int)(TG_STAGES * TG_STAGE * sizeof(__half)); // 92160B

__global__ void __launch_bounds__(256, 2)
tgemm(const __half* __restrict__ A, int lda, long Sa, long aSb, long aSh,
      const __half* __restrict__ B, int ldb, long bSb, long bSh,
      float* __restrict__ Cf, __half* __restrict__ Chi, long Sc,
      int ldc, long cSb, long cSh,
      int K, int H,
      const float* __restrict__ bias, const float* __restrict__ resid,
      const float* __restrict__ mask, int relu, int use_lo) {
    extern __shared__ __half smem[];

    int tid = threadIdx.x, wid = tid >> 5, lane = tid & 31;
    int warp_m = wid & 3, warp_n = wid >> 2;

    int z = blockIdx.z, zb = z / H, zh = z - zb * H;
    A += (long)zb * aSb + (long)zh * aSh;
    B += (long)zb * bSb + (long)zh * bSh;
    long cOff = (long)zb * cSb + (long)zh * cSh;
    if (Cf)    Cf += cOff;
    if (Chi)   Chi += cOff;
    if (resid) resid += cOff;
    int m0 = blockIdx.x * 128, n0 = blockIdx.y * 128;

    int lr = tid >> 2;            // 0..63 (+64 second row)
    int lc = (tid & 3) * 8;       // col (fp16 elems), 16B granules

    auto load_chunk = [&](int ci, int stg) {
        __half* S = smem + stg * TG_STAGE;
        int k0 = ci << 5;
        #pragma unroll
        for (int j = 0; j < 2; j++) {
            int r = lr + j * 64;
            long ak = (long)(m0 + r) * lda + k0 + lc;
            long bk = (long)(n0 + r) * ldb + k0 + lc;
            cp_async16(&S[r * TG_STRIDE + lc],                A + ak);
            if (use_lo) cp_async16(&S[TG_PLANE + r * TG_STRIDE + lc], A + Sa + ak);
            cp_async16(&S[2 * TG_PLANE + r * TG_STRIDE + lc], B + bk);
        }
        cp_commit();
    };

    float acc[2][8][4];
    #pragma unroll
    for (int a = 0; a < 2; a++)
        #pragma unroll
        for (int b = 0; b < 8; b++)
            #pragma unroll
            for (int c = 0; c < 4; c++) acc[a][b][c] = 0.f;

    int nc = K >> 5;
    load_chunk(0, 0);
    if (nc > 1) load_chunk(1, 1);

    int stg = 0;
    for (int i = 0; i < nc; i++) {
        if (i + 1 < nc) cp_wait<1>(); else cp_wait<0>();
        __syncthreads();
        if (i + 2 < nc) load_chunk(i + 2, (stg + 2) % TG_STAGES);

        const __half* Ss = smem + stg * TG_STAGE;
        #pragma unroll
        for (int ks = 0; ks < 2; ks++) {
            uint32_t ah[2][4], al[2][4];
            #pragma unroll
            for (int mt = 0; mt < 2; mt++) {
                int row = warp_m * 32 + mt * 16 + (lane & 15);
                int col = ks * 16 + ((lane >> 4) << 3);
                uint32_t ad = smem_u32(Ss + row * TG_STRIDE + col);
                ldm4(ah[mt], ad);
                if (use_lo) ldm4(al[mt], ad + TG_PLANE * 2);
            }
            #pragma unroll
            for (int tp = 0; tp < 4; tp++) {
                int row = warp_n * 64 + tp * 16 + ((lane >> 4) << 3) + (lane & 7);
                int col = ks * 16 + (((lane >> 3) & 1) << 3);
                uint32_t bd = smem_u32(Ss + 2 * TG_PLANE + row * TG_STRIDE + col);
                uint32_t bh[4];
                ldm4(bh, bd);
                #pragma unroll
                for (int mt = 0; mt < 2; mt++) {
                    #pragma unroll
                    for (int nt = 0; nt < 2; nt++) {
                        float* c = acc[mt][tp * 2 + nt];
                        mma16816(c, ah[mt], bh + nt * 2);
                        if (use_lo) mma16816(c, al[mt], bh + nt * 2);
                    }
                }
            }
        }
        stg = (stg + 1) % TG_STAGES;
    }

    // epilogue: direct stores
    #pragma unroll
    for (int mt = 0; mt < 2; mt++) {
        #pragma unroll
        for (int nt8 = 0; nt8 < 8; nt8++) {
            float* c = acc[mt][nt8];
            int row0 = m0 + warp_m * 32 + mt * 16 + (lane >> 2);
            int col  = n0 + warp_n * 64 + nt8 * 8 + (lane & 3) * 2;
            #pragma unroll
            for (int half = 0; half < 2; half++) {
                int m = row0 + half * 8;
                float v0 = c[half * 2], v1 = c[half * 2 + 1];
                if (bias) { v0 += bias[col]; v1 += bias[col + 1]; }
                if (relu) { v0 = fmaxf(v0, 0.f); v1 = fmaxf(v1, 0.f); }
                long co = (long)m * ldc + col;
                if (resid) { v0 += resid[co]; v1 += resid[co + 1]; }
                if (mask) { float mk = mask[m]; v0 *= mk; v1 *= mk; }
                if (Cf) { float2 o; o.x = v0; o.y = v1; *(float2*)(Cf + co) = o; }
                if (Chi) {
                    __half h0, l0, h1, l1;
                    split_h(v0, h0, l0); split_h(v1, h1, l1);
                    *(uint32_t*)(Chi + co)      = pack_h2(h0, h1);
                    *(uint32_t*)(Chi + Sc + co) = pack_h2(l0, l1);
                }
            }
        }
    }
}

// ---------------- host orchestration ----------------
extern "C" void kernel_launch(void* const* d_in, const int* in_sizes, int n_in,
                              void* d_out, int out_size) {
    const int*   src_seq  = (const int*)  d_in[0];
    const int*   src_pos  = (const int*)  d_in[1];
    const float* word_emb = (const float*)d_in[2];
    const float* pos_emb  = (const float*)d_in[3];
    const float* qkv_w    = (const float*)d_in[4];
    const float* qkv_b    = (const float*)d_in[5];
    const float* fc_w     = (const float*)d_in[6];
    const float* fc_b     = (const float*)d_in[7];
    const float* ln1_g    = (const float*)d_in[8];
    const float* ln1_b    = (const float*)d_in[9];
    const float* conv1_w  = (const float*)d_in[10];
    const float* conv1_b  = (const float*)d_in[11];
    const float* conv2_w  = (const float*)d_in[12];
    const float* conv2_b  = (const float*)d_in[13];
    const float* ln2_g    = (const float*)d_in[14];
    const float* ln2_b    = (const float*)d_in[15];

    float* x = (float*)d_out;

    cudaFuncSetAttribute(tgemm, cudaFuncAttributeMaxDynamicSharedMemorySize, TG_SMEM);

    __half *p_hcat, *p_qc, *p_kc, *p_vc, *p_pc, *p_aoc, *p_hpc, *p_hidc;
    __half *p_wqkv, *p_wfc, *p_w1, *p_w2;
    float *p_qkvf, *p_scf, *p_np;
    cudaGetSymbolAddress((void**)&p_hcat, g_hcat);
    cudaGetSymbolAddress((void**)&p_qkvf, g_qkvf);
    cudaGetSymbolAddress((void**)&p_qc,   g_qc);
    cudaGetSymbolAddress((void**)&p_kc,   g_kc);
    cudaGetSymbolAddress((void**)&p_vc,   g_vc);
    cudaGetSymbolAddress((void**)&p_scf,  g_scf);
    cudaGetSymbolAddress((void**)&p_pc,   g_pc);
    cudaGetSymbolAddress((void**)&p_aoc,  g_aoc);
    cudaGetSymbolAddress((void**)&p_hpc,  g_hpc);
    cudaGetSymbolAddress((void**)&p_hidc, g_hidc);
    cudaGetSymbolAddress((void**)&p_wqkv, g_wqkvc);
    cudaGetSymbolAddress((void**)&p_wfc,  g_wfcc);
    cudaGetSymbolAddress((void**)&p_w1,   g_w1c);
    cudaGetSymbolAddress((void**)&p_w2,   g_w2c);
    cudaGetSymbolAddress((void**)&p_np,   g_nonpad);

    // minimal prep before first GEMM (so ncu capture slot #4 = tgemm qkv)
    cvt_w_k<<<(int)((S_WQKV + 255) / 256), 256>>>(qkv_w, p_wqkv, S_WQKV);
    embed_k<<<M_ALL, D>>>(src_seq, src_pos, word_emb, pos_emb, x);

    for (int l = 0; l < L; l++) {
        // ---- attention ----
        ln_cat_k<<<M_ALL / 8, 256>>>(x, ln1_g + l * D, ln1_b + l * D, p_hcat, S_HCAT, 0);

        tgemm<<<dim3(M_ALL / 128, 6, 1), 256, TG_SMEM>>>(
            p_hcat, D, S_HCAT, 0, 0,
            p_wqkv + (long)l * 3 * D * D, D, 0, 0,
            p_qkvf, nullptr, 0, 3 * D, 0, 0,
            D, 1, qkv_b + (long)l * 3 * D, nullptr, nullptr, 0, 1);

        if (l == 0) {
            // rest of one-time prep (before first use below)
            zero_halo_k<<<(Bsz * 8 * D) / 256, 256>>>(p_hpc, S_HPC);
            cvt_w_k<<<(int)((S_WFC + 255) / 256), 256>>>(fc_w, p_wfc, S_WFC);
            cvt_w1_k<<<(int)((S_W1 + 255) / 256), 256>>>(conv1_w, p_w1);
            cvt_w_k<<<(int)((S_W2 + 255) / 256), 256>>>(conv2_w, p_w2, S_W2);
        }

        cvt_qkv_k<<<(int)(((long)M_ALL * 64 + 255) / 256), 256>>>(p_qkvf, p_qc, p_kc, p_vc, S_QC);

        tgemm<<<dim3(8, 8, BH), 256, TG_SMEM>>>(
            p_qc, DK, S_QC, (long)NH * T * DK, (long)T * DK,
            p_kc, DK, (long)NH * T * DK, (long)T * DK,
            p_scf, nullptr, 0, T, (long)NH * T * T, (long)T * T,
            DK, NH, nullptr, nullptr, nullptr, 0, 1);

        softmax_cat_k<<<BH * T, 256>>>(p_scf, src_seq, p_pc, S_PC);

        tgemm<<<dim3(8, 1, BH), 256, TG_SMEM>>>(
            p_pc, T, S_PC, (long)NH * T * T, (long)T * T,
            p_vc, T, (long)NH * DK * T, (long)DK * T,
            nullptr, p_aoc, S_AOC, D, (long)T * D, DK,
            T, NH, nullptr, nullptr, nullptr, 0, 1);

        tgemm<<<dim3(M_ALL / 128, 2, 1), 256, TG_SMEM>>>(
            p_aoc, D, S_AOC, 0, 0,
            p_wfc + (long)l * D * D, D, 0, 0,
            x, nullptr, 0, D, 0, 0,
            D, 1, fc_b + (long)l * D, x, p_np, 0, 1);

        // ---- conv FFN ----
        ln_cat_k<<<M_ALL / 8, 256>>>(x, ln2_g + l * D, ln2_b + l * D, p_hpc, S_HPC, 1);

        // conv1: hi-only pass (use_lo=0) — halves 69% of total MMA work
        tgemm<<<dim3(8, 8, Bsz), 256, TG_SMEM>>>(
            p_hpc, D, S_HPC, (long)TPAD * D, 0,
            p_w1 + (long)l * DH * D * 9, D * 9, 0, 0,
            nullptr, p_hidc, S_HIDC, DH, (long)T * DH, 0,
            D * 9, 1, conv1_b + (long)l * DH, nullptr, nullptr, 1, 0);

        tgemm<<<dim3(M_ALL / 128, 2, 1), 256, TG_SMEM>>>(
            p_hidc, DH, S_HIDC, 0, 0,
            p_w2 + (long)l * D * DH, DH, 0, 0,
            x, nullptr, 0, D, 0, 0,
            DH, 1, conv2_b + (long)l * D, x, p_np, 0, 1);
    }

    if (out_size >= M_ALL * D + M_ALL) {
        copy_np_k<<<M_ALL / 256, 256>>>((float*)d_out + (long)M_ALL * D);
    }
}

// round 15
// speedup vs baseline: 1.1346x; 1.0259x over previous
#include <cuda_runtime.h>
#include <cuda_fp16.h>
#include <cstdint>
#include <math.h>

// ---------------- problem constants ----------------
constexpr int Bsz = 32, T = 1024, D = 256, NH = 2, DK = 128, DH = 1024, L = 4;
constexpr int M_ALL = Bsz * T;          // 32768 rows
constexpr int TPAD  = T + 8;            // conv1 halo (4 each side)
constexpr int BH    = Bsz * NH;         // 64
constexpr float EPS = 1e-5f;

// plane strides (elements)
constexpr long S_HCAT = (long)M_ALL * D;
constexpr long S_QC   = (long)BH * T * DK;
constexpr long S_PC   = (long)BH * T * T;
constexpr long S_AOC  = (long)M_ALL * D;
constexpr long S_HPC  = (long)Bsz * TPAD * D;
constexpr long S_HIDC = (long)M_ALL * DH;
constexpr long S_WQKV = (long)L * 3 * D * D;
constexpr long S_WFC  = (long)L * D * D;
constexpr long S_W1   = (long)L * DH * D * 9;
constexpr long S_W2   = (long)L * D * DH;

// ---------------- device scratch ----------------
// A-role tensors keep hi+lo planes; B-role tensors hi only. P: hi only now.
__device__ __half g_hcat [2 * S_HCAT];
__device__ float  g_qkvf [(long)M_ALL * 3 * D];
__device__ __half g_qc   [2 * S_QC];
__device__ __half g_kc   [S_QC];          // B only (hi)
__device__ __half g_vc   [S_QC];          // B only (hi), transposed [bh][d][t]
__device__ float  g_scf  [(long)BH * T * T];
__device__ __half g_pc   [S_PC];          // P: single (hi) plane
__device__ __half g_aoc  [2 * S_AOC];
__device__ __half g_hpc  [2 * S_HPC];
__device__ __half g_hidc [2 * S_HIDC];
__device__ __half g_wqkvc[S_WQKV];        // weights: B only (hi)
__device__ __half g_wfcc [S_WFC];
__device__ __half g_w1c  [S_W1];
__device__ __half g_w2c  [S_W2];
__device__ float  g_nonpad[M_ALL];

// ---------------- mma/ldmatrix/cp.async helpers (portable sm_80+ ISA) -------
__device__ __forceinline__ uint32_t smem_u32(const void* p) {
    uint32_t a;
    asm("{ .reg .u64 t; cvta.to.shared.u64 t, %1; cvt.u32.u64 %0, t; }" : "=r"(a) : "l"(p));
    return a;
}
__device__ __forceinline__ void ldm4(uint32_t* r, uint32_t addr) {
    asm volatile("ldmatrix.sync.aligned.m8n8.x4.shared.b16 {%0,%1,%2,%3},[%4];"
                 : "=r"(r[0]), "=r"(r[1]), "=r"(r[2]), "=r"(r[3]) : "r"(addr));
}
__device__ __forceinline__ void mma16816(float* c, const uint32_t* a, const uint32_t* b) {
    asm volatile("mma.sync.aligned.m16n8k16.row.col.f32.f16.f16.f32 "
                 "{%0,%1,%2,%3},{%4,%5,%6,%7},{%8,%9},{%0,%1,%2,%3};"
                 : "+f"(c[0]), "+f"(c[1]), "+f"(c[2]), "+f"(c[3])
                 : "r"(a[0]), "r"(a[1]), "r"(a[2]), "r"(a[3]), "r"(b[0]), "r"(b[1]));
}
__device__ __forceinline__ void cp_async16(void* sp, const void* gp) {
    uint32_t s = smem_u32(sp);
    asm volatile("cp.async.ca.shared.global [%0], [%1], 16;" :: "r"(s), "l"(gp));
}
__device__ __forceinline__ void cp_commit() {
    asm volatile("cp.async.commit_group;" ::: "memory");
}
template <int N>
__device__ __forceinline__ void cp_wait() {
    asm volatile("cp.async.wait_group %0;" :: "n"(N) : "memory");
}

// ---------------- reductions ----------------
__device__ __forceinline__ float warpSum(float v) {
    #pragma unroll
    for (int o = 16; o; o >>= 1) v += __shfl_xor_sync(0xffffffffu, v, o);
    return v;
}
__device__ __forceinline__ float blockReduceSum(float v) {
    __shared__ float sh[8];
    int lane = threadIdx.x & 31, w = threadIdx.x >> 5;
    v = warpSum(v);
    if (!lane) sh[w] = v;
    __syncthreads();
    if (w == 0) {
        v = (lane < 8) ? sh[lane] : 0.f;
        #pragma unroll
        for (int o = 4; o; o >>= 1) v += __shfl_xor_sync(0xffffffffu, v, o);
        if (!lane) sh[0] = v;
    }
    __syncthreads();
    float r = sh[0];
    __syncthreads();
    return r;
}
__device__ __forceinline__ float blockReduceMax(float v) {
    __shared__ float sh[8];
    int lane = threadIdx.x & 31, w = threadIdx.x >> 5;
    #pragma unroll
    for (int o = 16; o; o >>= 1) v = fmaxf(v, __shfl_xor_sync(0xffffffffu, v, o));
    if (!lane) sh[w] = v;
    __syncthreads();
    if (w == 0) {
        v = (lane < 8) ? sh[lane] : -3.0e38f;
        #pragma unroll
        for (int o = 4; o; o >>= 1) v = fmaxf(v, __shfl_xor_sync(0xffffffffu, v, o));
        if (!lane) sh[0] = v;
    }
    __syncthreads();
    float r = sh[0];
    __syncthreads();
    return r;
}

__device__ __forceinline__ void split_h(float v, __half& h, __half& l) {
    h = __float2half(v);
    l = __float2half(v - __half2float(h));
}
__device__ __forceinline__ uint32_t pack_h2(__half a, __half b) {
    __half2 t; t.x = a; t.y = b;
    return *reinterpret_cast<uint32_t*>(&t);
}

// ---------------- small kernels ----------------
__global__ void embed_k(const int* __restrict__ seq, const int* __restrict__ pos,
                        const float* __restrict__ we, const float* __restrict__ pe,
                        float* __restrict__ x) {
    int r = blockIdx.x, d = threadIdx.x;
    int s = seq[r], p = pos[r];
    x[(long)r * D + d] = we[(long)s * D + d] + pe[(long)p * D + d];
    if (d == 0) g_nonpad[r] = (s != 0) ? 1.f : 0.f;
}

__global__ void ln_cat_k(const float* __restrict__ x, const float* __restrict__ g,
                         const float* __restrict__ bb, __half* __restrict__ out,
                         long S, int padmode) {
    int wid = threadIdx.x >> 5, lane = threadIdx.x & 31;
    long r = (long)blockIdx.x * 8 + wid;
    const float4* px = (const float4*)(x + r * D);
    float4 u = px[lane * 2], w = px[lane * 2 + 1];
    float vals[8] = {u.x, u.y, u.z, u.w, w.x, w.y, w.z, w.w};
    float s = 0.f;
    #pragma unroll
    for (int j = 0; j < 8; j++) s += vals[j];
    s = warpSum(s);
    float mean = s * (1.f / D);
    float q = 0.f;
    #pragma unroll
    for (int j = 0; j < 8; j++) { vals[j] -= mean; q += vals[j] * vals[j]; }
    q = warpSum(q);
    float rstd = rsqrtf(q * (1.f / D) + EPS);
    int col = lane * 8;
    const float4* pg = (const float4*)(g + col);
    const float4* pb = (const float4*)(bb + col);
    float4 g0 = pg[0], g1 = pg[1], b0 = pb[0], b1 = pb[1];
    float gg[8] = {g0.x, g0.y, g0.z, g0.w, g1.x, g1.y, g1.z, g1.w};
    float bbv[8] = {b0.x, b0.y, b0.z, b0.w, b1.x, b1.y, b1.z, b1.w};
    uint32_t hi[4], lo[4];
    #pragma unroll
    for (int j = 0; j < 4; j++) {
        float y0 = vals[2 * j] * rstd * gg[2 * j] + bbv[2 * j];
        float y1 = vals[2 * j + 1] * rstd * gg[2 * j + 1] + bbv[2 * j + 1];
        __half h0, l0, h1, l1;
        split_h(y0, h0, l0); split_h(y1, h1, l1);
        hi[j] = pack_h2(h0, h1); lo[j] = pack_h2(l0, l1);
    }
    long orow;
    if (padmode) { long b = r / T, t = r % T; orow = b * TPAD + t + 4; }
    else orow = r;
    long ob = orow * D + col;
    *(uint4*)(out + ob)      = *(uint4*)hi;
    *(uint4*)(out + S + ob)  = *(uint4*)lo;
}

__global__ void zero_halo_k(__half* __restrict__ hp, long S) {
    int idx = blockIdx.x * blockDim.x + threadIdx.x;
    int b = idx / (8 * D);
    int rr = (idx / D) % 8;
    int d = idx % D;
    int t = (rr < 4) ? rr : (T + 4 + rr - 4);
    long o = ((long)b * TPAD + t) * D + d;
    hp[o] = __float2half(0.f);
    hp[S + o] = __float2half(0.f);
}

// single-plane (hi) weight convert
__global__ void cvt_w_k(const float* __restrict__ w, __half* __restrict__ out, long n) {
    long i = (long)blockIdx.x * blockDim.x + threadIdx.x;
    if (i >= n) return;
    out[i] = __float2half(w[i]);
}

__global__ void cvt_w1_k(const float* __restrict__ w, __half* __restrict__ out) {
    long i = (long)blockIdx.x * blockDim.x + threadIdx.x;
    const long total = S_W1;
    if (i >= total) return;
    long base = i / (D * 9);
    int p = (int)(i % (D * 9));
    int kk = p / D, ii = p % D;
    out[i] = __float2half(w[base * (D * 9) + (long)ii * 9 + kk]);
}

// split qkv fp32 -> q (hi+lo), k (hi), v (hi, transposed [bh][d][t])
__global__ void cvt_qkv_k(const float* __restrict__ qkv,
                          __half* __restrict__ qc, __half* __restrict__ kc,
                          __half* __restrict__ vc, long S) {
    long idx = (long)blockIdx.x * blockDim.x + threadIdx.x;   // M_ALL*64
    long r = idx >> 6; int c4 = (int)(idx & 63);
    int b = (int)(r / T), t = (int)(r % T);
    int c = c4 * 4; int h = c >> 7; int d = c & 127;
    long src = r * (3 * D);
    float4 q = *(const float4*)(qkv + src + c);
    float4 k = *(const float4*)(qkv + src + D + c);
    float4 v = *(const float4*)(qkv + src + 2 * D + c);
    long bh = (long)b * NH + h;
    long qdst = (bh * T + t) * DK + d;
    {
        float a[4] = {q.x, q.y, q.z, q.w};
        __half hh[4], ll[4];
        #pragma unroll
        for (int j = 0; j < 4; j++) split_h(a[j], hh[j], ll[j]);
        uint32_t hu[2] = {pack_h2(hh[0], hh[1]), pack_h2(hh[2], hh[3])};
        uint32_t lu[2] = {pack_h2(ll[0], ll[1]), pack_h2(ll[2], ll[3])};
        *(uint2*)(qc + qdst) = *(uint2*)hu;
        *(uint2*)(qc + S + qdst) = *(uint2*)lu;
    }
    {
        uint32_t hu[2] = {pack_h2(__float2half(k.x), __float2half(k.y)),
                          pack_h2(__float2half(k.z), __float2half(k.w))};
        *(uint2*)(kc + qdst) = *(uint2*)hu;
    }
    {
        float a[4] = {v.x, v.y, v.z, v.w};
        #pragma unroll
        for (int j = 0; j < 4; j++) {
            long vdst = (bh * DK + d + j) * T + t;
            vc[vdst] = __float2half(a[j]);
        }
    }
}

// softmax: fp32 scores -> single-plane fp16 P
__global__ void softmax_cat_k(const float* __restrict__ sc, const int* __restrict__ seq,
                              __half* __restrict__ out) {
    long row = blockIdx.x;
    int b = (int)(row / ((long)NH * T));
    const float* p = sc + row * T;
    const int* sq = seq + (long)b * T;
    const float scale = 0.08838834764831845f;
    int t = threadIdx.x;
    float4 v4 = *(const float4*)(p + t * 4);
    int4 s4 = *(const int4*)(sq + t * 4);
    float vals[4] = {v4.x, v4.y, v4.z, v4.w};
    int ss[4] = {s4.x, s4.y, s4.z, s4.w};
    float mx = -3.0e38f;
    #pragma unroll
    for (int j = 0; j < 4; j++) {
        vals[j] = (ss[j] == 0) ? -3.0e38f : vals[j] * scale;
        mx = fmaxf(mx, vals[j]);
    }
    float M = blockReduceMax(mx);
    float s = 0.f;
    #pragma unroll
    for (int j = 0; j < 4; j++) { vals[j] = __expf(vals[j] - M); s += vals[j]; }
    float Ssum = blockReduceSum(s);
    float inv = 1.f / Ssum;
    uint32_t hu[2] = {pack_h2(__float2half(vals[0] * inv), __float2half(vals[1] * inv)),
                      pack_h2(__float2half(vals[2] * inv), __float2half(vals[3] * inv))};
    long ob = row * T + t * 4;
    *(uint2*)(out + ob) = *(uint2*)hu;
}

__global__ void copy_np_k(float* __restrict__ out) {
    int i = blockIdx.x * blockDim.x + threadIdx.x;
    if (i < M_ALL) out[i] = g_nonpad[i];
}

// ---------------- HMMA split-fp16 GEMM, cp.async.ca 3-stage -----------------
// C[m,n] = sum_k A[m,k]*B[n,k]; A has hi(+lo) planes (stride Sa), B hi only.
// use_lo: 1 = two passes (hi*hi + lo_a*hi_b); 0 = hi*hi only (half the MMAs).
// Tile 128x128, 8 warps (4x2 grid, warp tile 32x64), K-chunk 32.
// __launch_bounds__(256, 2): cap regs at 128 so TWO CTAs co-reside per SM.
constexpr int TG_STRIDE = 40;                       // fp16 elems per smem row (pad)
constexpr int TG_PLANE  = 128 * TG_STRIDE;          // elems per plane
constexpr int TG_STAGE  = 3 * TG_PLANE;             // Ahi, Alo, Bhi per stage
constexpr int TG_STAGES = 3;
constexpr int TG_SMEM   = (int)(TG_STAGES * TG_STAGE * sizeof(__half)); // 92160B

__global__ void __launch_bounds__(256, 2)
tgemm(const __half* __restrict__ A, int lda, long Sa, long aSb, long aSh,
      const __half* __restrict__ B, int ldb, long bSb, long bSh,
      float* __restrict__ Cf, __half* __restrict__ Chi, long Sc,
      int ldc, long cSb, long cSh,
      int K, int H,
      const float* __restrict__ bias, const float* __restrict__ resid,
      const float* __restrict__ mask, int relu, int use_lo) {
    extern __shared__ __half smem[];

    int tid = threadIdx.x, wid = tid >> 5, lane = tid & 31;
    int warp_m = wid & 3, warp_n = wid >> 2;

    int z = blockIdx.z, zb = z / H, zh = z - zb * H;
    A += (long)zb * aSb + (long)zh * aSh;
    B += (long)zb * bSb + (long)zh * bSh;
    long cOff = (long)zb * cSb + (long)zh * cSh;
    if (Cf)    Cf += cOff;
    if (Chi)   Chi += cOff;
    if (resid) resid += cOff;
    int m0 = blockIdx.x * 128, n0 = blockIdx.y * 128;

    int lr = tid >> 2;            // 0..63 (+64 second row)
    int lc = (tid & 3) * 8;       // col (fp16 elems), 16B granules

    auto load_chunk = [&](int ci, int stg) {
        __half* S = smem + stg * TG_STAGE;
        int k0 = ci << 5;
        #pragma unroll
        for (int j = 0; j < 2; j++) {
            int r = lr + j * 64;
            long ak = (long)(m0 + r) * lda + k0 + lc;
            long bk = (long)(n0 + r) * ldb + k0 + lc;
            cp_async16(&S[r * TG_STRIDE + lc],                A + ak);
            if (use_lo) cp_async16(&S[TG_PLANE + r * TG_STRIDE + lc], A + Sa + ak);
            cp_async16(&S[2 * TG_PLANE + r * TG_STRIDE + lc], B + bk);
        }
        cp_commit();
    };

    float acc[2][8][4];
    #pragma unroll
    for (int a = 0; a < 2; a++)
        #pragma unroll
        for (int b = 0; b < 8; b++)
            #pragma unroll
            for (int c = 0; c < 4; c++) acc[a][b][c] = 0.f;

    int nc = K >> 5;
    load_chunk(0, 0);
    if (nc > 1) load_chunk(1, 1);

    int stg = 0;
    for (int i = 0; i < nc; i++) {
        if (i + 1 < nc) cp_wait<1>(); else cp_wait<0>();
        __syncthreads();
        if (i + 2 < nc) load_chunk(i + 2, (stg + 2) % TG_STAGES);

        const __half* Ss = smem + stg * TG_STAGE;
        #pragma unroll
        for (int ks = 0; ks < 2; ks++) {
            uint32_t ah[2][4], al[2][4];
            #pragma unroll
            for (int mt = 0; mt < 2; mt++) {
                int row = warp_m * 32 + mt * 16 + (lane & 15);
                int col = ks * 16 + ((lane >> 4) << 3);
                uint32_t ad = smem_u32(Ss + row * TG_STRIDE + col);
                ldm4(ah[mt], ad);
                if (use_lo) ldm4(al[mt], ad + TG_PLANE * 2);
            }
            #pragma unroll
            for (int tp = 0; tp < 4; tp++) {
                int row = warp_n * 64 + tp * 16 + ((lane >> 4) << 3) + (lane & 7);
                int col = ks * 16 + (((lane >> 3) & 1) << 3);
                uint32_t bd = smem_u32(Ss + 2 * TG_PLANE + row * TG_STRIDE + col);
                uint32_t bh[4];
                ldm4(bh, bd);
                #pragma unroll
                for (int mt = 0; mt < 2; mt++) {
                    #pragma unroll
                    for (int nt = 0; nt < 2; nt++) {
                        float* c = acc[mt][tp * 2 + nt];
                        mma16816(c, ah[mt], bh + nt * 2);
                        if (use_lo) mma16816(c, al[mt], bh + nt * 2);
                    }
                }
            }
        }
        stg = (stg + 1) % TG_STAGES;
    }

    // epilogue: direct stores
    #pragma unroll
    for (int mt = 0; mt < 2; mt++) {
        #pragma unroll
        for (int nt8 = 0; nt8 < 8; nt8++) {
            float* c = acc[mt][nt8];
            int row0 = m0 + warp_m * 32 + mt * 16 + (lane >> 2);
            int col  = n0 + warp_n * 64 + nt8 * 8 + (lane & 3) * 2;
            #pragma unroll
            for (int half = 0; half < 2; half++) {
                int m = row0 + half * 8;
                float v0 = c[half * 2], v1 = c[half * 2 + 1];
                if (bias) { v0 += bias[col]; v1 += bias[col + 1]; }
                if (relu) { v0 = fmaxf(v0, 0.f); v1 = fmaxf(v1, 0.f); }
                long co = (long)m * ldc + col;
                if (resid) { v0 += resid[co]; v1 += resid[co + 1]; }
                if (mask) { float mk = mask[m]; v0 *= mk; v1 *= mk; }
                if (Cf) { float2 o; o.x = v0; o.y = v1; *(float2*)(Cf + co) = o; }
                if (Chi) {
                    __half h0, l0, h1, l1;
                    split_h(v0, h0, l0); split_h(v1, h1, l1);
                    *(uint32_t*)(Chi + co)      = pack_h2(h0, h1);
                    *(uint32_t*)(Chi + Sc + co) = pack_h2(l0, l1);
                }
            }
        }
    }
}

// ---------------- host orchestration ----------------
extern "C" void kernel_launch(void* const* d_in, const int* in_sizes, int n_in,
                              void* d_out, int out_size) {
    const int*   src_seq  = (const int*)  d_in[0];
    const int*   src_pos  = (const int*)  d_in[1];
    const float* word_emb = (const float*)d_in[2];
    const float* pos_emb  = (const float*)d_in[3];
    const float* qkv_w    = (const float*)d_in[4];
    const float* qkv_b    = (const float*)d_in[5];
    const float* fc_w     = (const float*)d_in[6];
    const float* fc_b     = (const float*)d_in[7];
    const float* ln1_g    = (const float*)d_in[8];
    const float* ln1_b    = (const float*)d_in[9];
    const float* conv1_w  = (const float*)d_in[10];
    const float* conv1_b  = (const float*)d_in[11];
    const float* conv2_w  = (const float*)d_in[12];
    const float* conv2_b  = (const float*)d_in[13];
    const float* ln2_g    = (const float*)d_in[14];
    const float* ln2_b    = (const float*)d_in[15];

    float* x = (float*)d_out;

    cudaFuncSetAttribute(tgemm, cudaFuncAttributeMaxDynamicSharedMemorySize, TG_SMEM);

    __half *p_hcat, *p_qc, *p_kc, *p_vc, *p_pc, *p_aoc, *p_hpc, *p_hidc;
    __half *p_wqkv, *p_wfc, *p_w1, *p_w2;
    float *p_qkvf, *p_scf, *p_np;
    cudaGetSymbolAddress((void**)&p_hcat, g_hcat);
    cudaGetSymbolAddress((void**)&p_qkvf, g_qkvf);
    cudaGetSymbolAddress((void**)&p_qc,   g_qc);
    cudaGetSymbolAddress((void**)&p_kc,   g_kc);
    cudaGetSymbolAddress((void**)&p_vc,   g_vc);
    cudaGetSymbolAddress((void**)&p_scf,  g_scf);
    cudaGetSymbolAddress((void**)&p_pc,   g_pc);
    cudaGetSymbolAddress((void**)&p_aoc,  g_aoc);
    cudaGetSymbolAddress((void**)&p_hpc,  g_hpc);
    cudaGetSymbolAddress((void**)&p_hidc, g_hidc);
    cudaGetSymbolAddress((void**)&p_wqkv, g_wqkvc);
    cudaGetSymbolAddress((void**)&p_wfc,  g_wfcc);
    cudaGetSymbolAddress((void**)&p_w1,   g_w1c);
    cudaGetSymbolAddress((void**)&p_w2,   g_w2c);
    cudaGetSymbolAddress((void**)&p_np,   g_nonpad);

    // minimal prep before first GEMM (so ncu capture slot #4 = tgemm qkv)
    cvt_w_k<<<(int)((S_WQKV + 255) / 256), 256>>>(qkv_w, p_wqkv, S_WQKV);
    embed_k<<<M_ALL, D>>>(src_seq, src_pos, word_emb, pos_emb, x);

    for (int l = 0; l < L; l++) {
        // ---- attention ----
        ln_cat_k<<<M_ALL / 8, 256>>>(x, ln1_g + l * D, ln1_b + l * D, p_hcat, S_HCAT, 0);

        tgemm<<<dim3(M_ALL / 128, 6, 1), 256, TG_SMEM>>>(
            p_hcat, D, S_HCAT, 0, 0,
            p_wqkv + (long)l * 3 * D * D, D, 0, 0,
            p_qkvf, nullptr, 0, 3 * D, 0, 0,
            D, 1, qkv_b + (long)l * 3 * D, nullptr, nullptr, 0, 1);

        if (l == 0) {
            // rest of one-time prep (before first use below)
            zero_halo_k<<<(Bsz * 8 * D) / 256, 256>>>(p_hpc, S_HPC);
            cvt_w_k<<<(int)((S_WFC + 255) / 256), 256>>>(fc_w, p_wfc, S_WFC);
            cvt_w1_k<<<(int)((S_W1 + 255) / 256), 256>>>(conv1_w, p_w1);
            cvt_w_k<<<(int)((S_W2 + 255) / 256), 256>>>(conv2_w, p_w2, S_W2);
        }

        cvt_qkv_k<<<(int)(((long)M_ALL * 64 + 255) / 256), 256>>>(p_qkvf, p_qc, p_kc, p_vc, S_QC);

        tgemm<<<dim3(8, 8, BH), 256, TG_SMEM>>>(
            p_qc, DK, S_QC, (long)NH * T * DK, (long)T * DK,
            p_kc, DK, (long)NH * T * DK, (long)T * DK,
            p_scf, nullptr, 0, T, (long)NH * T * T, (long)T * T,
            DK, NH, nullptr, nullptr, nullptr, 0, 1);

        softmax_cat_k<<<BH * T, 256>>>(p_scf, src_seq, p_pc);

        // P·V with single-plane P (use_lo = 0)
        tgemm<<<dim3(8, 1, BH), 256, TG_SMEM>>>(
            p_pc, T, 0, (long)NH * T * T, (long)T * T,
            p_vc, T, (long)NH * DK * T, (long)DK * T,
            nullptr, p_aoc, S_AOC, D, (long)T * D, DK,
            T, NH, nullptr, nullptr, nullptr, 0, 0);

        tgemm<<<dim3(M_ALL / 128, 2, 1), 256, TG_SMEM>>>(
            p_aoc, D, S_AOC, 0, 0,
            p_wfc + (long)l * D * D, D, 0, 0,
            x, nullptr, 0, D, 0, 0,
            D, 1, fc_b + (long)l * D, x, p_np, 0, 1);

        // ---- conv FFN ----
        ln_cat_k<<<M_ALL / 8, 256>>>(x, ln2_g + l * D, ln2_b + l * D, p_hpc, S_HPC, 1);

        // conv1: hi-only pass (use_lo=0)
        tgemm<<<dim3(8, 8, Bsz), 256, TG_SMEM>>>(
            p_hpc, D, S_HPC, (long)TPAD * D, 0,
            p_w1 + (long)l * DH * D * 9, D * 9, 0, 0,
            nullptr, p_hidc, S_HIDC, DH, (long)T * DH, 0,
            D * 9, 1, conv1_b + (long)l * DH, nullptr, nullptr, 1, 0);

        tgemm<<<dim3(M_ALL / 128, 2, 1), 256, TG_SMEM>>>(
            p_hidc, DH, S_HIDC, 0, 0,
            p_w2 + (long)l * D * DH, DH, 0, 0,
            x, nullptr, 0, D, 0, 0,
            DH, 1, conv2_b + (long)l * D, x, p_np, 0, 1);
    }

    if (out_size >= M_ALL * D + M_ALL) {
        copy_np_k<<<M_ALL / 256, 256>>>((float*)d_out + (long)M_ALL * D);
    }
}

// round 16
// speedup vs baseline: 1.1579x; 1.0205x over previous
#include <cuda_runtime.h>
#include <cuda_fp16.h>
#include <cstdint>
#include <math.h>

// ---------------- problem constants ----------------
constexpr int Bsz = 32, T = 1024, D = 256, NH = 2, DK = 128, DH = 1024, L = 4;
constexpr int M_ALL = Bsz * T;          // 32768 rows
constexpr int TPAD  = T + 8;            // conv1 halo (4 each side)
constexpr int BH    = Bsz * NH;         // 64
constexpr float EPS = 1e-5f;

// plane strides (elements)
constexpr long S_HCAT = (long)M_ALL * D;
constexpr long S_QC   = (long)BH * T * DK;
constexpr long S_PC   = (long)BH * T * T;
constexpr long S_AOC  = (long)M_ALL * D;
constexpr long S_HPC  = (long)Bsz * TPAD * D;
constexpr long S_HIDC = (long)M_ALL * DH;
constexpr long S_WQKV = (long)L * 3 * D * D;
constexpr long S_WFC  = (long)L * D * D;
constexpr long S_W1   = (long)L * DH * D * 9;
constexpr long S_W2   = (long)L * D * DH;

// ---------------- device scratch ----------------
__device__ __half g_hcat [S_HCAT];        // LN1 out: hi only (qkv is hi-only)
__device__ float  g_qkvf [(long)M_ALL * 3 * D];
__device__ __half g_qc   [2 * S_QC];      // Q: hi+lo (scores stays 2-pass)
__device__ __half g_kc   [S_QC];          // K: hi
__device__ __half g_vc   [S_QC];          // V: hi, transposed [bh][d][t]
__device__ __half g_sch  [S_PC];          // scores: fp16 now
__device__ __half g_pc   [S_PC];          // P: hi
__device__ __half g_aoc  [2 * S_AOC];     // attn out: hi+lo (fc stays 2-pass)
__device__ __half g_hpc  [S_HPC];         // LN2 out: hi only (conv1 hi-only)
__device__ __half g_hidc [S_HIDC];        // conv1 out: hi only (conv2 hi-only)
__device__ __half g_wqkvc[S_WQKV];
__device__ __half g_wfcc [S_WFC];
__device__ __half g_w1c  [S_W1];
__device__ __half g_w2c  [S_W2];
__device__ float  g_nonpad[M_ALL];

// ---------------- mma/ldmatrix/cp.async helpers (portable sm_80+ ISA) -------
__device__ __forceinline__ uint32_t smem_u32(const void* p) {
    uint32_t a;
    asm("{ .reg .u64 t; cvta.to.shared.u64 t, %1; cvt.u32.u64 %0, t; }" : "=r"(a) : "l"(p));
    return a;
}
__device__ __forceinline__ void ldm4(uint32_t* r, uint32_t addr) {
    asm volatile("ldmatrix.sync.aligned.m8n8.x4.shared.b16 {%0,%1,%2,%3},[%4];"
                 : "=r"(r[0]), "=r"(r[1]), "=r"(r[2]), "=r"(r[3]) : "r"(addr));
}
__device__ __forceinline__ void mma16816(float* c, const uint32_t* a, const uint32_t* b) {
    asm volatile("mma.sync.aligned.m16n8k16.row.col.f32.f16.f16.f32 "
                 "{%0,%1,%2,%3},{%4,%5,%6,%7},{%8,%9},{%0,%1,%2,%3};"
                 : "+f"(c[0]), "+f"(c[1]), "+f"(c[2]), "+f"(c[3])
                 : "r"(a[0]), "r"(a[1]), "r"(a[2]), "r"(a[3]), "r"(b[0]), "r"(b[1]));
}
__device__ __forceinline__ void cp_async16(void* sp, const void* gp) {
    uint32_t s = smem_u32(sp);
    asm volatile("cp.async.ca.shared.global [%0], [%1], 16;" :: "r"(s), "l"(gp));
}
__device__ __forceinline__ void cp_commit() {
    asm volatile("cp.async.commit_group;" ::: "memory");
}
template <int N>
__device__ __forceinline__ void cp_wait() {
    asm volatile("cp.async.wait_group %0;" :: "n"(N) : "memory");
}

// ---------------- reductions ----------------
__device__ __forceinline__ float warpSum(float v) {
    #pragma unroll
    for (int o = 16; o; o >>= 1) v += __shfl_xor_sync(0xffffffffu, v, o);
    return v;
}
__device__ __forceinline__ float blockReduceSum(float v) {
    __shared__ float sh[8];
    int lane = threadIdx.x & 31, w = threadIdx.x >> 5;
    v = warpSum(v);
    if (!lane) sh[w] = v;
    __syncthreads();
    if (w == 0) {
        v = (lane < 8) ? sh[lane] : 0.f;
        #pragma unroll
        for (int o = 4; o; o >>= 1) v += __shfl_xor_sync(0xffffffffu, v, o);
        if (!lane) sh[0] = v;
    }
    __syncthreads();
    float r = sh[0];
    __syncthreads();
    return r;
}
__device__ __forceinline__ float blockReduceMax(float v) {
    __shared__ float sh[8];
    int lane = threadIdx.x & 31, w = threadIdx.x >> 5;
    #pragma unroll
    for (int o = 16; o; o >>= 1) v = fmaxf(v, __shfl_xor_sync(0xffffffffu, v, o));
    if (!lane) sh[w] = v;
    __syncthreads();
    if (w == 0) {
        v = (lane < 8) ? sh[lane] : -3.0e38f;
        #pragma unroll
        for (int o = 4; o; o >>= 1) v = fmaxf(v, __shfl_xor_sync(0xffffffffu, v, o));
        if (!lane) sh[0] = v;
    }
    __syncthreads();
    float r = sh[0];
    __syncthreads();
    return r;
}

__device__ __forceinline__ void split_h(float v, __half& h, __half& l) {
    h = __float2half(v);
    l = __float2half(v - __half2float(h));
}
__device__ __forceinline__ uint32_t pack_h2(__half a, __half b) {
    __half2 t; t.x = a; t.y = b;
    return *reinterpret_cast<uint32_t*>(&t);
}

// ---------------- small kernels ----------------
__global__ void embed_k(const int* __restrict__ seq, const int* __restrict__ pos,
                        const float* __restrict__ we, const float* __restrict__ pe,
                        float* __restrict__ x) {
    int r = blockIdx.x, d = threadIdx.x;
    int s = seq[r], p = pos[r];
    x[(long)r * D + d] = we[(long)s * D + d] + pe[(long)p * D + d];
    if (d == 0) g_nonpad[r] = (s != 0) ? 1.f : 0.f;
}

// LN -> single (hi) fp16 plane
__global__ void ln_cat_k(const float* __restrict__ x, const float* __restrict__ g,
                         const float* __restrict__ bb, __half* __restrict__ out,
                         int padmode) {
    int wid = threadIdx.x >> 5, lane = threadIdx.x & 31;
    long r = (long)blockIdx.x * 8 + wid;
    const float4* px = (const float4*)(x + r * D);
    float4 u = px[lane * 2], w = px[lane * 2 + 1];
    float vals[8] = {u.x, u.y, u.z, u.w, w.x, w.y, w.z, w.w};
    float s = 0.f;
    #pragma unroll
    for (int j = 0; j < 8; j++) s += vals[j];
    s = warpSum(s);
    float mean = s * (1.f / D);
    float q = 0.f;
    #pragma unroll
    for (int j = 0; j < 8; j++) { vals[j] -= mean; q += vals[j] * vals[j]; }
    q = warpSum(q);
    float rstd = rsqrtf(q * (1.f / D) + EPS);
    int col = lane * 8;
    const float4* pg = (const float4*)(g + col);
    const float4* pb = (const float4*)(bb + col);
    float4 g0 = pg[0], g1 = pg[1], b0 = pb[0], b1 = pb[1];
    float gg[8] = {g0.x, g0.y, g0.z, g0.w, g1.x, g1.y, g1.z, g1.w};
    float bbv[8] = {b0.x, b0.y, b0.z, b0.w, b1.x, b1.y, b1.z, b1.w};
    uint32_t hi[4];
    #pragma unroll
    for (int j = 0; j < 4; j++) {
        float y0 = vals[2 * j] * rstd * gg[2 * j] + bbv[2 * j];
        float y1 = vals[2 * j + 1] * rstd * gg[2 * j + 1] + bbv[2 * j + 1];
        hi[j] = pack_h2(__float2half(y0), __float2half(y1));
    }
    long orow;
    if (padmode) { long b = r / T, t = r % T; orow = b * TPAD + t + 4; }
    else orow = r;
    *(uint4*)(out + orow * D + col) = *(uint4*)hi;
}

__global__ void zero_halo_k(__half* __restrict__ hp) {
    int idx = blockIdx.x * blockDim.x + threadIdx.x;
    int b = idx / (8 * D);
    int rr = (idx / D) % 8;
    int d = idx % D;
    int t = (rr < 4) ? rr : (T + 4 + rr - 4);
    hp[((long)b * TPAD + t) * D + d] = __float2half(0.f);
}

__global__ void cvt_w_k(const float* __restrict__ w, __half* __restrict__ out, long n) {
    long i = (long)blockIdx.x * blockDim.x + threadIdx.x;
    if (i >= n) return;
    out[i] = __float2half(w[i]);
}

__global__ void cvt_w1_k(const float* __restrict__ w, __half* __restrict__ out) {
    long i = (long)blockIdx.x * blockDim.x + threadIdx.x;
    const long total = S_W1;
    if (i >= total) return;
    long base = i / (D * 9);
    int p = (int)(i % (D * 9));
    int kk = p / D, ii = p % D;
    out[i] = __float2half(w[base * (D * 9) + (long)ii * 9 + kk]);
}

// split qkv fp32 -> q (hi+lo), k (hi), v (hi, transposed [bh][d][t])
__global__ void cvt_qkv_k(const float* __restrict__ qkv,
                          __half* __restrict__ qc, __half* __restrict__ kc,
                          __half* __restrict__ vc, long S) {
    long idx = (long)blockIdx.x * blockDim.x + threadIdx.x;   // M_ALL*64
    long r = idx >> 6; int c4 = (int)(idx & 63);
    int b = (int)(r / T), t = (int)(r % T);
    int c = c4 * 4; int h = c >> 7; int d = c & 127;
    long src = r * (3 * D);
    float4 q = *(const float4*)(qkv + src + c);
    float4 k = *(const float4*)(qkv + src + D + c);
    float4 v = *(const float4*)(qkv + src + 2 * D + c);
    long bh = (long)b * NH + h;
    long qdst = (bh * T + t) * DK + d;
    {
        float a[4] = {q.x, q.y, q.z, q.w};
        __half hh[4], ll[4];
        #pragma unroll
        for (int j = 0; j < 4; j++) split_h(a[j], hh[j], ll[j]);
        uint32_t hu[2] = {pack_h2(hh[0], hh[1]), pack_h2(hh[2], hh[3])};
        uint32_t lu[2] = {pack_h2(ll[0], ll[1]), pack_h2(ll[2], ll[3])};
        *(uint2*)(qc + qdst) = *(uint2*)hu;
        *(uint2*)(qc + S + qdst) = *(uint2*)lu;
    }
    {
        uint32_t hu[2] = {pack_h2(__float2half(k.x), __float2half(k.y)),
                          pack_h2(__float2half(k.z), __float2half(k.w))};
        *(uint2*)(kc + qdst) = *(uint2*)hu;
    }
    {
        float a[4] = {v.x, v.y, v.z, v.w};
        #pragma unroll
        for (int j = 0; j < 4; j++) {
            long vdst = (bh * DK + d + j) * T + t;
            vc[vdst] = __float2half(a[j]);
        }
    }
}

// softmax: fp16 scores -> single-plane fp16 P
__global__ void softmax_cat_k(const __half* __restrict__ sc, const int* __restrict__ seq,
                              __half* __restrict__ out) {
    long row = blockIdx.x;
    int b = (int)(row / ((long)NH * T));
    const __half* p = sc + row * T;
    const int* sq = seq + (long)b * T;
    const float scale = 0.08838834764831845f;
    int t = threadIdx.x;
    uint2 raw = *(const uint2*)(p + t * 4);
    __half2 h01 = *reinterpret_cast<__half2*>(&raw.x);
    __half2 h23 = *reinterpret_cast<__half2*>(&raw.y);
    int4 s4 = *(const int4*)(sq + t * 4);
    float vals[4] = {__half2float(h01.x), __half2float(h01.y),
                     __half2float(h23.x), __half2float(h23.y)};
    int ss[4] = {s4.x, s4.y, s4.z, s4.w};
    float mx = -3.0e38f;
    #pragma unroll
    for (int j = 0; j < 4; j++) {
        vals[j] = (ss[j] == 0) ? -3.0e38f : vals[j] * scale;
        mx = fmaxf(mx, vals[j]);
    }
    float M = blockReduceMax(mx);
    float s = 0.f;
    #pragma unroll
    for (int j = 0; j < 4; j++) { vals[j] = __expf(vals[j] - M); s += vals[j]; }
    float Ssum = blockReduceSum(s);
    float inv = 1.f / Ssum;
    uint32_t hu[2] = {pack_h2(__float2half(vals[0] * inv), __float2half(vals[1] * inv)),
                      pack_h2(__float2half(vals[2] * inv), __float2half(vals[3] * inv))};
    long ob = row * T + t * 4;
    *(uint2*)(out + ob) = *(uint2*)hu;
}

__global__ void copy_np_k(float* __restrict__ out) {
    int i = blockIdx.x * blockDim.x + threadIdx.x;
    if (i < M_ALL) out[i] = g_nonpad[i];
}

// ---------------- HMMA split-fp16 GEMM, cp.async.ca 3-stage -----------------
// C[m,n] = sum_k A[m,k]*B[n,k]; A hi(+lo if use_lo), B hi only.
// Chi: fp16 output (hi plane; +lo plane iff Sc != 0). Cf: fp32 output.
// Tile 128x128, 8 warps (4x2), warp tile 32x64, K-chunk 32, 2 CTAs/SM.
constexpr int TG_STRIDE = 40;
constexpr int TG_PLANE  = 128 * TG_STRIDE;
constexpr int TG_STAGE  = 3 * TG_PLANE;
constexpr int TG_STAGES = 3;
constexpr int TG_SMEM   = (int)(TG_STAGES * TG_STAGE * sizeof(__half)); // 92160B

__global__ void __launch_bounds__(256, 2)
tgemm(const __half* __restrict__ A, int lda, long Sa, long aSb, long aSh,
      const __half* __restrict__ B, int ldb, long bSb, long bSh,
      float* __restrict__ Cf, __half* __restrict__ Chi, long Sc,
      int ldc, long cSb, long cSh,
      int K, int H,
      const float* __restrict__ bias, const float* __restrict__ resid,
      const float* __restrict__ mask, int relu, int use_lo) {
    extern __shared__ __half smem[];

    int tid = threadIdx.x, wid = tid >> 5, lane = tid & 31;
    int warp_m = wid & 3, warp_n = wid >> 2;

    int z = blockIdx.z, zb = z / H, zh = z - zb * H;
    A += (long)zb * aSb + (long)zh * aSh;
    B += (long)zb * bSb + (long)zh * bSh;
    long cOff = (long)zb * cSb + (long)zh * cSh;
    if (Cf)    Cf += cOff;
    if (Chi)   Chi += cOff;
    if (resid) resid += cOff;
    int m0 = blockIdx.x * 128, n0 = blockIdx.y * 128;

    int lr = tid >> 2;
    int lc = (tid & 3) * 8;

    auto load_chunk = [&](int ci, int stg) {
        __half* S = smem + stg * TG_STAGE;
        int k0 = ci << 5;
        #pragma unroll
        for (int j = 0; j < 2; j++) {
            int r = lr + j * 64;
            long ak = (long)(m0 + r) * lda + k0 + lc;
            long bk = (long)(n0 + r) * ldb + k0 + lc;
            cp_async16(&S[r * TG_STRIDE + lc],                A + ak);
            if (use_lo) cp_async16(&S[TG_PLANE + r * TG_STRIDE + lc], A + Sa + ak);
            cp_async16(&S[2 * TG_PLANE + r * TG_STRIDE + lc], B + bk);
        }
        cp_commit();
    };

    float acc[2][8][4];
    #pragma unroll
    for (int a = 0; a < 2; a++)
        #pragma unroll
        for (int b = 0; b < 8; b++)
            #pragma unroll
            for (int c = 0; c < 4; c++) acc[a][b][c] = 0.f;

    int nc = K >> 5;
    load_chunk(0, 0);
    if (nc > 1) load_chunk(1, 1);

    int stg = 0;
    for (int i = 0; i < nc; i++) {
        if (i + 1 < nc) cp_wait<1>(); else cp_wait<0>();
        __syncthreads();
        if (i + 2 < nc) load_chunk(i + 2, (stg + 2) % TG_STAGES);

        const __half* Ss = smem + stg * TG_STAGE;
        #pragma unroll
        for (int ks = 0; ks < 2; ks++) {
            uint32_t ah[2][4], al[2][4];
            #pragma unroll
            for (int mt = 0; mt < 2; mt++) {
                int row = warp_m * 32 + mt * 16 + (lane & 15);
                int col = ks * 16 + ((lane >> 4) << 3);
                uint32_t ad = smem_u32(Ss + row * TG_STRIDE + col);
                ldm4(ah[mt], ad);
                if (use_lo) ldm4(al[mt], ad + TG_PLANE * 2);
            }
            #pragma unroll
            for (int tp = 0; tp < 4; tp++) {
                int row = warp_n * 64 + tp * 16 + ((lane >> 4) << 3) + (lane & 7);
                int col = ks * 16 + (((lane >> 3) & 1) << 3);
                uint32_t bd = smem_u32(Ss + 2 * TG_PLANE + row * TG_STRIDE + col);
                uint32_t bh[4];
                ldm4(bh, bd);
                #pragma unroll
                for (int mt = 0; mt < 2; mt++) {
                    #pragma unroll
                    for (int nt = 0; nt < 2; nt++) {
                        float* c = acc[mt][tp * 2 + nt];
                        mma16816(c, ah[mt], bh + nt * 2);
                        if (use_lo) mma16816(c, al[mt], bh + nt * 2);
                    }
                }
            }
        }
        stg = (stg + 1) % TG_STAGES;
    }

    // epilogue
    #pragma unroll
    for (int mt = 0; mt < 2; mt++) {
        #pragma unroll
        for (int nt8 = 0; nt8 < 8; nt8++) {
            float* c = acc[mt][nt8];
            int row0 = m0 + warp_m * 32 + mt * 16 + (lane >> 2);
            int col  = n0 + warp_n * 64 + nt8 * 8 + (lane & 3) * 2;
            #pragma unroll
            for (int half = 0; half < 2; half++) {
                int m = row0 + half * 8;
                float v0 = c[half * 2], v1 = c[half * 2 + 1];
                if (bias) { v0 += bias[col]; v1 += bias[col + 1]; }
                if (relu) { v0 = fmaxf(v0, 0.f); v1 = fmaxf(v1, 0.f); }
                long co = (long)m * ldc + col;
                if (resid) { v0 += resid[co]; v1 += resid[co + 1]; }
                if (mask) { float mk = mask[m]; v0 *= mk; v1 *= mk; }
                if (Cf) { float2 o; o.x = v0; o.y = v1; *(float2*)(Cf + co) = o; }
                if (Chi) {
                    if (Sc) {
                        __half h0, l0, h1, l1;
                        split_h(v0, h0, l0); split_h(v1, h1, l1);
                        *(uint32_t*)(Chi + co)      = pack_h2(h0, h1);
                        *(uint32_t*)(Chi + Sc + co) = pack_h2(l0, l1);
                    } else {
                        *(uint32_t*)(Chi + co) = pack_h2(__float2half(v0), __float2half(v1));
                    }
                }
            }
        }
    }
}

// ---------------- host orchestration ----------------
extern "C" void kernel_launch(void* const* d_in, const int* in_sizes, int n_in,
                              void* d_out, int out_size) {
    const int*   src_seq  = (const int*)  d_in[0];
    const int*   src_pos  = (const int*)  d_in[1];
    const float* word_emb = (const float*)d_in[2];
    const float* pos_emb  = (const float*)d_in[3];
    const float* qkv_w    = (const float*)d_in[4];
    const float* qkv_b    = (const float*)d_in[5];
    const float* fc_w     = (const float*)d_in[6];
    const float* fc_b     = (const float*)d_in[7];
    const float* ln1_g    = (const float*)d_in[8];
    const float* ln1_b    = (const float*)d_in[9];
    const float* conv1_w  = (const float*)d_in[10];
    const float* conv1_b  = (const float*)d_in[11];
    const float* conv2_w  = (const float*)d_in[12];
    const float* conv2_b  = (const float*)d_in[13];
    const float* ln2_g    = (const float*)d_in[14];
    const float* ln2_b    = (const float*)d_in[15];

    float* x = (float*)d_out;

    cudaFuncSetAttribute(tgemm, cudaFuncAttributeMaxDynamicSharedMemorySize, TG_SMEM);

    __half *p_hcat, *p_qc, *p_kc, *p_vc, *p_sch, *p_pc, *p_aoc, *p_hpc, *p_hidc;
    __half *p_wqkv, *p_wfc, *p_w1, *p_w2;
    float *p_qkvf, *p_np;
    cudaGetSymbolAddress((void**)&p_hcat, g_hcat);
    cudaGetSymbolAddress((void**)&p_qkvf, g_qkvf);
    cudaGetSymbolAddress((void**)&p_qc,   g_qc);
    cudaGetSymbolAddress((void**)&p_kc,   g_kc);
    cudaGetSymbolAddress((void**)&p_vc,   g_vc);
    cudaGetSymbolAddress((void**)&p_sch,  g_sch);
    cudaGetSymbolAddress((void**)&p_pc,   g_pc);
    cudaGetSymbolAddress((void**)&p_aoc,  g_aoc);
    cudaGetSymbolAddress((void**)&p_hpc,  g_hpc);
    cudaGetSymbolAddress((void**)&p_hidc, g_hidc);
    cudaGetSymbolAddress((void**)&p_wqkv, g_wqkvc);
    cudaGetSymbolAddress((void**)&p_wfc,  g_wfcc);
    cudaGetSymbolAddress((void**)&p_w1,   g_w1c);
    cudaGetSymbolAddress((void**)&p_w2,   g_w2c);
    cudaGetSymbolAddress((void**)&p_np,   g_nonpad);

    // minimal prep before first GEMM
    cvt_w_k<<<(int)((S_WQKV + 255) / 256), 256>>>(qkv_w, p_wqkv, S_WQKV);
    embed_k<<<M_ALL, D>>>(src_seq, src_pos, word_emb, pos_emb, x);

    for (int l = 0; l < L; l++) {
        // ---- attention ----
        ln_cat_k<<<M_ALL / 8, 256>>>(x, ln1_g + l * D, ln1_b + l * D, p_hcat, 0);

        // qkv: hi-only
        tgemm<<<dim3(M_ALL / 128, 6, 1), 256, TG_SMEM>>>(
            p_hcat, D, 0, 0, 0,
            p_wqkv + (long)l * 3 * D * D, D, 0, 0,
            p_qkvf, nullptr, 0, 3 * D, 0, 0,
            D, 1, qkv_b + (long)l * 3 * D, nullptr, nullptr, 0, 0);

        if (l == 0) {
            zero_halo_k<<<(Bsz * 8 * D) / 256, 256>>>(p_hpc);
            cvt_w_k<<<(int)((S_WFC + 255) / 256), 256>>>(fc_w, p_wfc, S_WFC);
            cvt_w1_k<<<(int)((S_W1 + 255) / 256), 256>>>(conv1_w, p_w1);
            cvt_w_k<<<(int)((S_W2 + 255) / 256), 256>>>(conv2_w, p_w2, S_W2);
        }

        cvt_qkv_k<<<(int)(((long)M_ALL * 64 + 255) / 256), 256>>>(p_qkvf, p_qc, p_kc, p_vc, S_QC);

        // scores: 2-pass, fp16 output
        tgemm<<<dim3(8, 8, BH), 256, TG_SMEM>>>(
            p_qc, DK, S_QC, (long)NH * T * DK, (long)T * DK,
            p_kc, DK, (long)NH * T * DK, (long)T * DK,
            nullptr, p_sch, 0, T, (long)NH * T * T, (long)T * T,
            DK, NH, nullptr, nullptr, nullptr, 0, 1);

        softmax_cat_k<<<BH * T, 256>>>(p_sch, src_seq, p_pc);

        // P·V: hi-only, writes aoc hi+lo (fc corrects A-side)
        tgemm<<<dim3(8, 1, BH), 256, TG_SMEM>>>(
            p_pc, T, 0, (long)NH * T * T, (long)T * T,
            p_vc, T, (long)NH * DK * T, (long)DK * T,
            nullptr, p_aoc, S_AOC, D, (long)T * D, DK,
            T, NH, nullptr, nullptr, nullptr, 0, 0);

        // fc: 2-pass + bias + residual + mask -> x
        tgemm<<<dim3(M_ALL / 128, 2, 1), 256, TG_SMEM>>>(
            p_aoc, D, S_AOC, 0, 0,
            p_wfc + (long)l * D * D, D, 0, 0,
            x, nullptr, 0, D, 0, 0,
            D, 1, fc_b + (long)l * D, x, p_np, 0, 1);

        // ---- conv FFN ----
        ln_cat_k<<<M_ALL / 8, 256>>>(x, ln2_g + l * D, ln2_b + l * D, p_hpc, 1);

        // conv1: hi-only, fp16 hi-only output
        tgemm<<<dim3(8, 8, Bsz), 256, TG_SMEM>>>(
            p_hpc, D, 0, (long)TPAD * D, 0,
            p_w1 + (long)l * DH * D * 9, D * 9, 0, 0,
            nullptr, p_hidc, 0, DH, (long)T * DH, 0,
            D * 9, 1, conv1_b + (long)l * DH, nullptr, nullptr, 1, 0);

        // conv2: hi-only + bias + residual + mask -> x
        tgemm<<<dim3(M_ALL / 128, 2, 1), 256, TG_SMEM>>>(
            p_hidc, DH, 0, 0, 0,
            p_w2 + (long)l * D * DH, DH, 0, 0,
            x, nullptr, 0, D, 0, 0,
            DH, 1, conv2_b + (long)l * D, x, p_np, 0, 0);
    }

    if (out_size >= M_ALL * D + M_ALL) {
        copy_np_k<<<M_ALL / 256, 256>>>((float*)d_out + (long)M_ALL * D);
    }
}